// round 10
// baseline (speedup 1.0000x reference)
#include <cuda_runtime.h>
#include <cuda_bf16.h>
#include <math.h>
#include <stdint.h>

#define NPEDS_MAX 8192
#define H 256
#define E 64
#define G4 1024   // 4*H
#define KTOT 320  // E + H
#define SEQ 30
#define KT_TILES 10  // KTOT/32

// ---- device-global scratch (no allocations allowed) ----
// h double-buffered: step s reads buf (s&1), writes buf ((s+1)&1).
__device__ __align__(16) __nv_bfloat16 g_h[2][NPEDS_MAX * H];
__device__ __align__(16) float g_hf[NPEDS_MAX * H];          // fp32 h for tail LN2
__device__ __align__(16) float g_c[NPEDS_MAX * H];
__device__ __align__(16) __nv_bfloat16 g_x[NPEDS_MAX * E];
__device__ __align__(16) __nv_bfloat16 g_Wn[G4 * KTOT];  // [n'][k], n' = ch*4+gate
__device__ __align__(16) float g_bias4[G4];              // [ch][gate] interleaved

__device__ __forceinline__ float sigm(float v) { return 1.f / (1.f + __expf(-v)); }
__device__ __forceinline__ float tanh_fast(float v) {
  return 2.f / (1.f + __expf(-2.f * v)) - 1.f;
}

// ---------------------------------------------------------------------------
// Init kernels (run every graph replay -> deterministic state reset)
// ---------------------------------------------------------------------------
__global__ void prep_weights(const float* __restrict__ W_ih, const float* __restrict__ W_hh,
                             const float* __restrict__ b_ih, const float* __restrict__ b_hh) {
  int idx = blockIdx.x * blockDim.x + threadIdx.x;
  if (idx < G4 * KTOT) {
    int np = idx / KTOT, k = idx - np * KTOT;
    int n = (np & 3) * 256 + (np >> 2);       // gate-major original row
    float w = (k < E) ? W_ih[n * E + k] : W_hh[n * H + (k - E)];
    g_Wn[idx] = __float2bfloat16(w);
  }
  if (idx < G4) {
    int gate = idx & 3, ch = idx >> 2;
    int n = gate * 256 + ch;
    g_bias4[idx] = b_ih[n] + b_hh[n];
  }
}

__global__ void init_state(const float* __restrict__ h0, const float* __restrict__ c0, int n) {
  int idx = blockIdx.x * blockDim.x + threadIdx.x;
  if (idx < n) {
    g_h[0][idx] = __float2bfloat16(h0[idx]);
    g_c[idx] = c0[idx];
  }
}

// embed(p) = leaky_relu( LN_2(p) @ emb_W^T + emb_b )
__global__ void embed_init(const float* __restrict__ lpr,
                           const float* __restrict__ ln1_g, const float* __restrict__ ln1_b,
                           const float* __restrict__ emb_W, const float* __restrict__ emb_b,
                           int npeds) {
  int idx = blockIdx.x * blockDim.x + threadIdx.x;
  if (idx >= npeds * E) return;
  int ped = idx / E, j = idx - ped * E;
  float a = lpr[ped * 2 + 0], b = lpr[ped * 2 + 1];
  float d = 0.5f * (a - b);
  float inv = rsqrtf(d * d + 1e-5f);
  float na =  d * inv * ln1_g[0] + ln1_b[0];
  float nb = -d * inv * ln1_g[1] + ln1_b[1];
  float y = na * emb_W[j * 2 + 0] + nb * emb_W[j * 2 + 1] + emb_b[j];
  g_x[idx] = __float2bfloat16((y > 0.f) ? y : 0.01f * y);
}

// ---------------------------------------------------------------------------
// Fused GEMM + LSTM (race-free via h double-buffer; coalesced smem epilogue;
// fast MUFU activations; c tile prefetched via its own cp.async group).
// BM=128, BN=128(=32 ch), BK=32, 8 warps (2m x 4n), mma.m16n8k16.bf16.
// Dynamic smem layout (bytes):
//   [0, 40960)        pipeline: As[2][128][20], Bs[2][128][20] (uint32)
//   [40960, 59392)    CS: float[128][36]  (144B rows, 16B-aligned)
//   [59392, 77824)    HS: float[128][36]
// ---------------------------------------------------------------------------
#define PIPE_U (128 * 20)             // uint32 per tile buffer
#define CS_OFF 40960
#define HS_OFF 59392
#define SMEM_BYTES 77824

__global__ __launch_bounds__(256, 2) void gates_step(int rdbuf, int npeds) {
  extern __shared__ __align__(16) char smraw[];
  uint32_t* const As0 = (uint32_t*)smraw;                 // [2][128][20]
  uint32_t* const Bs0 = (uint32_t*)smraw + 2 * PIPE_U;    // [2][128][20]
  float* const CS = (float*)(smraw + CS_OFF);             // [128][36]
  float* const HS = (float*)(smraw + HS_OFF);             // [128][36]

  const __nv_bfloat16* __restrict__ h_rd = g_h[rdbuf];
  __nv_bfloat16* __restrict__ h_wr = g_h[rdbuf ^ 1];

  const int bm = blockIdx.y * 128;
  const int bn = blockIdx.x * 128;
  const int chbase = bn >> 2;          // 32 channels per CTA
  const int t = threadIdx.x;
  const int warp = t >> 5;
  const int lane = t & 31;
  const int wm = (warp >> 2) * 64;
  const int wn = (warp & 3) * 32;
  const int gr = lane >> 2;   // 0..7
  const int lc = lane & 3;    // 0..3

  float acc[4][4][4];
#pragma unroll
  for (int i = 0; i < 4; ++i)
#pragma unroll
    for (int j = 0; j < 4; ++j)
#pragma unroll
      for (int q = 0; q < 4; ++q) acc[i][j][q] = 0.f;

  // ---- group 0: prefetch c tile [128][32] -> CS (never touched by pipeline)
  {
    const uint32_t csb = (uint32_t)__cvta_generic_to_shared(CS);
#pragma unroll
    for (int i = 0; i < 4; ++i) {
      const int ci = t + i * 256;          // 0..1023 chunks of 16B
      const int row = ci >> 3, ch4 = ci & 7;
      const float* gc = g_c + (size_t)(bm + row) * H + chbase + ch4 * 4;
      asm volatile("cp.async.cg.shared.global [%0], [%1], 16;"
                   :: "r"(csb + row * 144 + ch4 * 16), "l"(gc));
    }
    asm volatile("cp.async.commit_group;");
  }

  const int mm0 = t >> 2;          // 0..63
  const int c4 = t & 3;            // 16B chunk

  auto load_tile = [&](int kt, int buf) {
    const int k0 = kt * 32;
    const __nv_bfloat16* srcA;
    int ldk, koff;
    if (k0 < E) { srcA = g_x; ldk = E; koff = k0; }
    else        { srcA = h_rd; ldk = H; koff = k0 - E; }
#pragma unroll
    for (int r = 0; r < 2; ++r) {
      const int mm = mm0 + r * 64;
      const void* gA = srcA + (size_t)(bm + mm) * ldk + koff + c4 * 8;
      uint32_t dA = (uint32_t)__cvta_generic_to_shared(&As0[buf * PIPE_U + mm * 20 + c4 * 4]);
      asm volatile("cp.async.cg.shared.global [%0], [%1], 16;\n" :: "r"(dA), "l"(gA));
      const void* gB = g_Wn + (size_t)(bn + mm) * KTOT + k0 + c4 * 8;
      uint32_t dB = (uint32_t)__cvta_generic_to_shared(&Bs0[buf * PIPE_U + mm * 20 + c4 * 4]);
      asm volatile("cp.async.cg.shared.global [%0], [%1], 16;\n" :: "r"(dB), "l"(gB));
    }
    asm volatile("cp.async.commit_group;\n");
  };

  load_tile(0, 0);

  for (int kt = 0; kt < KT_TILES; ++kt) {
    asm volatile("cp.async.wait_group 0;\n");
    __syncthreads();
    if (kt + 1 < KT_TILES) load_tile(kt + 1, (kt + 1) & 1);
    const int buf = kt & 1;
    const uint32_t* Ab = &As0[buf * PIPE_U];
    const uint32_t* Bb = &Bs0[buf * PIPE_U];

#pragma unroll
    for (int ks = 0; ks < 2; ++ks) {
      const int kb = ks * 8;
      uint32_t a[4][4], b[4][2];
#pragma unroll
      for (int mt = 0; mt < 4; ++mt) {
        const int ar = wm + mt * 16 + gr;
        a[mt][0] = Ab[ar * 20 + kb + lc];
        a[mt][1] = Ab[(ar + 8) * 20 + kb + lc];
        a[mt][2] = Ab[ar * 20 + kb + lc + 4];
        a[mt][3] = Ab[(ar + 8) * 20 + kb + lc + 4];
      }
#pragma unroll
      for (int nt = 0; nt < 4; ++nt) {
        const int br = wn + nt * 8 + gr;
        b[nt][0] = Bb[br * 20 + kb + lc];
        b[nt][1] = Bb[br * 20 + kb + lc + 4];
      }
#pragma unroll
      for (int mt = 0; mt < 4; ++mt)
#pragma unroll
        for (int nt = 0; nt < 4; ++nt) {
          asm volatile(
            "mma.sync.aligned.m16n8k16.row.col.f32.bf16.bf16.f32 "
            "{%0,%1,%2,%3}, {%4,%5,%6,%7}, {%8,%9}, {%0,%1,%2,%3};"
            : "+f"(acc[mt][nt][0]), "+f"(acc[mt][nt][1]),
              "+f"(acc[mt][nt][2]), "+f"(acc[mt][nt][3])
            : "r"(a[mt][0]), "r"(a[mt][1]), "r"(a[mt][2]), "r"(a[mt][3]),
              "r"(b[nt][0]), "r"(b[nt][1]));
        }
    }
  }

  // ================= fused LSTM epilogue =================
  __syncthreads();   // pipeline dead; CS already filled by group-0 prefetch

  // Per-thread gate math. Columns gate-interleaved: lc even -> (i,f),
  // lc odd -> (g,o); shfl_xor(1) pairs lanes; even lane row gr, odd row gr+8.
  const bool odd = (lc & 1);
#pragma unroll
  for (int mt = 0; mt < 4; ++mt) {
    const int rowL = wm + mt * 16 + gr + (odd ? 8 : 0);
#pragma unroll
    for (int nt = 0; nt < 4; ++nt) {
      const float q0 = acc[mt][nt][0], q1 = acc[mt][nt][1];
      const float q2 = acc[mt][nt][2], q3 = acc[mt][nt][3];
      const float v0 = __shfl_xor_sync(0xffffffffu, q0, 1);
      const float v1 = __shfl_xor_sync(0xffffffffu, q1, 1);
      const float v2 = __shfl_xor_sync(0xffffffffu, q2, 1);
      const float v3 = __shfl_xor_sync(0xffffffffu, q3, 1);
      const float gi = odd ? v2 : q0;
      const float gf = odd ? v3 : q1;
      const float gg = odd ? q2 : v0;
      const float go = odd ? q3 : v1;
      const int chL = ((wn + nt * 8) >> 2) + (lc >> 1);
      const float4 bi = *(const float4*)&g_bias4[(chbase + chL) * 4];
      const float cv = CS[rowL * 36 + chL];
      const float cn = sigm(gf + bi.y) * cv + sigm(gi + bi.x) * tanh_fast(gg + bi.z);
      const float hv = sigm(go + bi.w) * tanh_fast(cn);
      CS[rowL * 36 + chL] = cn;
      HS[rowL * 36 + chL] = hv;
    }
  }
  __syncthreads();

  // Coalesced writeback
#pragma unroll
  for (int r = 0; r < 16; ++r) {
    const int row = r * 8 + warp;
    const size_t off = (size_t)(bm + row) * H + chbase + lane;
    g_c[off] = CS[row * 36 + lane];
    g_hf[off] = HS[row * 36 + lane];
  }
#pragma unroll
  for (int r = 0; r < 8; ++r) {
    const int row = r * 16 + warp * 2 + (lane >> 4);
    const int ch2 = lane & 15;
    __nv_bfloat162 v = __floats2bfloat162_rn(HS[row * 36 + ch2 * 2],
                                             HS[row * 36 + ch2 * 2 + 1]);
    *(__nv_bfloat162*)(h_wr + (size_t)(bm + row) * H + chbase + ch2 * 2) = v;
  }
}

// ---------------------------------------------------------------------------
// Per-step tail: LN2 + pos projection (rel out) + embed(rel) -> next x.
// ---------------------------------------------------------------------------
__global__ __launch_bounds__(256) void ln_proj_embed(
    const float* __restrict__ ln2_g, const float* __restrict__ ln2_b,
    const float* __restrict__ pos_W, const float* __restrict__ pos_b,
    const float* __restrict__ emb_W, const float* __restrict__ emb_b,
    const float* __restrict__ ln1_g, const float* __restrict__ ln1_b,
    float* __restrict__ rel_out, int npeds) {
  const int warp = threadIdx.x >> 5;
  const int lane = threadIdx.x & 31;
  const int ped = blockIdx.x * 8 + warp;
  if (ped >= npeds) return;

  const float* hp = g_hf + (size_t)ped * H + lane * 8;
  float hn[8];
  {
    float4 u0 = *(const float4*)hp;
    float4 u1 = *(const float4*)(hp + 4);
    hn[0] = u0.x; hn[1] = u0.y; hn[2] = u0.z; hn[3] = u0.w;
    hn[4] = u1.x; hn[5] = u1.y; hn[6] = u1.z; hn[7] = u1.w;
  }
  float s = 0.f, ss = 0.f;
#pragma unroll
  for (int q = 0; q < 8; ++q) { s += hn[q]; ss += hn[q] * hn[q]; }
#pragma unroll
  for (int o = 16; o > 0; o >>= 1) {
    s += __shfl_xor_sync(0xffffffffu, s, o);
    ss += __shfl_xor_sync(0xffffffffu, ss, o);
  }
  const float mu = s * (1.f / 256.f);
  const float var = ss * (1.f / 256.f) - mu * mu;
  const float rstd = rsqrtf(var + 1e-5f);

  float d0 = 0.f, d1 = 0.f;
  const int ch0 = lane * 8;
#pragma unroll
  for (int q = 0; q < 8; ++q) {
    const float nh = (hn[q] - mu) * rstd * ln2_g[ch0 + q] + ln2_b[ch0 + q];
    d0 += nh * pos_W[ch0 + q];
    d1 += nh * pos_W[256 + ch0 + q];
  }
#pragma unroll
  for (int o = 16; o > 0; o >>= 1) {
    d0 += __shfl_xor_sync(0xffffffffu, d0, o);
    d1 += __shfl_xor_sync(0xffffffffu, d1, o);
  }
  const float r0 = sigm(d0 + pos_b[0]);
  const float r1 = sigm(d1 + pos_b[1]);
  if (lane == 0) {
    rel_out[(size_t)ped * 2 + 0] = r0;
    rel_out[(size_t)ped * 2 + 1] = r1;
  }

  const float d = 0.5f * (r0 - r1);
  const float inv = rsqrtf(d * d + 1e-5f);
  const float na =  d * inv * ln1_g[0] + ln1_b[0];
  const float nb = -d * inv * ln1_g[1] + ln1_b[1];
  __nv_bfloat16* xp = g_x + (size_t)ped * E;
#pragma unroll
  for (int q = 0; q < 2; ++q) {
    const int j = lane * 2 + q;
    const float y = na * emb_W[j * 2 + 0] + nb * emb_W[j * 2 + 1] + emb_b[j];
    xp[j] = __float2bfloat16((y > 0.f) ? y : 0.01f * y);
  }
}

// ---------------------------------------------------------------------------
extern "C" void kernel_launch(void* const* d_in, const int* in_sizes, int n_in,
                              void* d_out, int out_size) {
  const float* last_pos_rel = (const float*)d_in[1];
  const float* h0   = (const float*)d_in[2];
  const float* c0   = (const float*)d_in[3];
  const float* W_ih = (const float*)d_in[4];
  const float* W_hh = (const float*)d_in[5];
  const float* b_ih = (const float*)d_in[6];
  const float* b_hh = (const float*)d_in[7];
  const float* emb_W = (const float*)d_in[8];
  const float* emb_b = (const float*)d_in[9];
  const float* ln1_g = (const float*)d_in[10];
  const float* ln1_b = (const float*)d_in[11];
  const float* pos_W = (const float*)d_in[12];
  const float* pos_b = (const float*)d_in[13];
  const float* ln2_g = (const float*)d_in[14];
  const float* ln2_b = (const float*)d_in[15];
  float* out = (float*)d_out;

  const int npeds = in_sizes[0] / 2;  // 8192

  static int smem_set = 0;
  if (!smem_set) {
    cudaFuncSetAttribute(gates_step, cudaFuncAttributeMaxDynamicSharedMemorySize,
                         SMEM_BYTES);
    smem_set = 1;
  }

  prep_weights<<<(G4 * KTOT + 255) / 256, 256>>>(W_ih, W_hh, b_ih, b_hh);
  init_state<<<(npeds * H + 255) / 256, 256>>>(h0, c0, npeds * H);
  embed_init<<<(npeds * E + 255) / 256, 256>>>(last_pos_rel, ln1_g, ln1_b, emb_W, emb_b, npeds);

  dim3 ggrid(G4 / 128, npeds / 128);
  for (int s = 0; s < SEQ; ++s) {
    gates_step<<<ggrid, 256, SMEM_BYTES>>>(s & 1, npeds);
    ln_proj_embed<<<npeds / 8, 256>>>(ln2_g, ln2_b, pos_W, pos_b, emb_W, emb_b,
                                      ln1_g, ln1_b, out + (size_t)s * npeds * 2, npeds);
  }
}

// round 11
// speedup vs baseline: 1.3752x; 1.3752x over previous
#include <cuda_runtime.h>
#include <cuda_bf16.h>
#include <math.h>
#include <stdint.h>

#define NPEDS_MAX 8192
#define H 256
#define E 64
#define G4 1024   // 4*H
#define KTOT 320  // E + H
#define SEQ 30
#define KT_TILES 10  // KTOT/32

// ---- device-global scratch (no allocations allowed) ----
__device__ __align__(16) __nv_bfloat16 g_h[NPEDS_MAX * H];
__device__ float g_c[NPEDS_MAX * H];
__device__ __align__(16) __nv_bfloat16 g_x[NPEDS_MAX * E];
__device__ float g_gates[NPEDS_MAX * G4];
__device__ __align__(16) __nv_bfloat16 g_Wn[G4 * KTOT];  // [n][k] bf16, gate-major n
__device__ float g_bias[G4];

__device__ __forceinline__ float sigm(float v) { return 1.f / (1.f + __expf(-v)); }
__device__ __forceinline__ float tanh_fast(float v) {
  return 2.f / (1.f + __expf(-2.f * v)) - 1.f;
}

// ---------------------------------------------------------------------------
// Init kernels (run every graph replay -> deterministic state reset)
// ---------------------------------------------------------------------------
__global__ void prep_weights(const float* __restrict__ W_ih, const float* __restrict__ W_hh,
                             const float* __restrict__ b_ih, const float* __restrict__ b_hh) {
  int idx = blockIdx.x * blockDim.x + threadIdx.x;
  if (idx < G4 * KTOT) {
    int n = idx / KTOT, k = idx - n * KTOT;
    float w = (k < E) ? W_ih[n * E + k] : W_hh[n * H + (k - E)];
    g_Wn[idx] = __float2bfloat16(w);
  }
  if (idx < G4) g_bias[idx] = b_ih[idx] + b_hh[idx];
}

__global__ void init_state(const float* __restrict__ h0, const float* __restrict__ c0, int n) {
  int idx = blockIdx.x * blockDim.x + threadIdx.x;
  if (idx < n) { g_h[idx] = __float2bfloat16(h0[idx]); g_c[idx] = c0[idx]; }
}

// embed(p) = leaky_relu( LN_2(p) @ emb_W^T + emb_b )
__global__ void embed_init(const float* __restrict__ lpr,
                           const float* __restrict__ ln1_g, const float* __restrict__ ln1_b,
                           const float* __restrict__ emb_W, const float* __restrict__ emb_b,
                           int npeds) {
  int idx = blockIdx.x * blockDim.x + threadIdx.x;
  if (idx >= npeds * E) return;
  int ped = idx / E, j = idx - ped * E;
  float a = lpr[ped * 2 + 0], b = lpr[ped * 2 + 1];
  float d = 0.5f * (a - b);
  float inv = rsqrtf(d * d + 1e-5f);
  float na =  d * inv * ln1_g[0] + ln1_b[0];
  float nb = -d * inv * ln1_g[1] + ln1_b[1];
  float y = na * emb_W[j * 2 + 0] + nb * emb_W[j * 2 + 1] + emb_b[j];
  g_x[idx] = __float2bfloat16((y > 0.f) ? y : 0.01f * y);
}

// ---------------------------------------------------------------------------
// Per-step GEMM (bf16 MMA + ldmatrix fragment loads, 2-stage cp.async):
//   g_gates[M,1024] = [x|h][M,320] @ Wn^T  (Wn stored [n][k])
// BM=128, BN=128, BK=32. 8 warps (2m x 4n), warp tile 64x32, mma.m16n8k16.
// 80B smem rows: LDSM-conflict-free (row starts hit disjoint 4-bank spans).
// ---------------------------------------------------------------------------
__global__ __launch_bounds__(256, 2) void gates_gemm(int npeds) {
  __shared__ __align__(16) uint32_t As[2][128][20];  // [m][k-pairs]
  __shared__ __align__(16) uint32_t Bs[2][128][20];  // [n][k-pairs]

  const int bm = blockIdx.y * 128;
  const int bn = blockIdx.x * 128;
  const int t = threadIdx.x;
  const int warp = t >> 5;
  const int lane = t & 31;
  const int wm = (warp >> 2) * 64;
  const int wn = (warp & 3) * 32;
  const int gr = lane >> 2;   // 0..7  (store epilogue)
  const int lc = lane & 3;    // 0..3

  // ldmatrix lane addressing (per 8x8 b16 matrix: 8 row pointers from 8 lanes)
  const int lg = lane >> 3;       // lane group 0..3
  const int lr = lane & 7;        // row within group
  // A x4: g0: rows 0-7 chunk0 | g1: rows 8-15 chunk0 | g2: rows 0-7 chunk1 | g3: rows 8-15 chunk1
  const uint32_t aLane = (uint32_t)__cvta_generic_to_shared(
      &As[0][wm + (lg & 1) * 8 + lr][(lg >> 1) * 4]);
  // B x4 (nt pair): g0: n 0-7 chunk0 | g1: n 0-7 chunk1 | g2: n 8-15 chunk0 | g3: n 8-15 chunk1
  const uint32_t bLane = (uint32_t)__cvta_generic_to_shared(
      &Bs[0][wn + (lg >> 1) * 8 + lr][(lg & 1) * 4]);

  float acc[4][4][4];
#pragma unroll
  for (int i = 0; i < 4; ++i)
#pragma unroll
    for (int j = 0; j < 4; ++j)
#pragma unroll
      for (int q = 0; q < 4; ++q) acc[i][j][q] = 0.f;

  const int mm0 = t >> 2;          // 0..63
  const int c4 = t & 3;            // 16B chunk

  auto load_tile = [&](int kt, int buf) {
    const int k0 = kt * 32;
    const __nv_bfloat16* srcA;
    int ldk, koff;
    if (k0 < E) { srcA = g_x; ldk = E; koff = k0; }
    else        { srcA = g_h; ldk = H; koff = k0 - E; }
#pragma unroll
    for (int r = 0; r < 2; ++r) {
      const int mm = mm0 + r * 64;
      const void* gA = srcA + (size_t)(bm + mm) * ldk + koff + c4 * 8;
      uint32_t dA = (uint32_t)__cvta_generic_to_shared(&As[buf][mm][c4 * 4]);
      asm volatile("cp.async.cg.shared.global [%0], [%1], 16;\n" :: "r"(dA), "l"(gA));
      const void* gB = g_Wn + (size_t)(bn + mm) * KTOT + k0 + c4 * 8;
      uint32_t dB = (uint32_t)__cvta_generic_to_shared(&Bs[buf][mm][c4 * 4]);
      asm volatile("cp.async.cg.shared.global [%0], [%1], 16;\n" :: "r"(dB), "l"(gB));
    }
    asm volatile("cp.async.commit_group;\n");
  };

  load_tile(0, 0);

  for (int kt = 0; kt < KT_TILES; ++kt) {
    asm volatile("cp.async.wait_group 0;\n");
    __syncthreads();
    if (kt + 1 < KT_TILES) load_tile(kt + 1, (kt + 1) & 1);
    const int buf = kt & 1;
    const uint32_t bufOff = (uint32_t)buf * 10240u;   // 128*20*4 bytes

#pragma unroll
    for (int ks = 0; ks < 2; ++ks) {
      const uint32_t kOff = bufOff + (uint32_t)ks * 32u;
      uint32_t a[4][4], b[4][2];
#pragma unroll
      for (int mt = 0; mt < 4; ++mt) {
        asm volatile(
          "ldmatrix.sync.aligned.m8n8.x4.shared.b16 {%0,%1,%2,%3}, [%4];"
          : "=r"(a[mt][0]), "=r"(a[mt][1]), "=r"(a[mt][2]), "=r"(a[mt][3])
          : "r"(aLane + kOff + (uint32_t)mt * 1280u));   // 16 rows * 80B
      }
#pragma unroll
      for (int p = 0; p < 2; ++p) {
        asm volatile(
          "ldmatrix.sync.aligned.m8n8.x4.shared.b16 {%0,%1,%2,%3}, [%4];"
          : "=r"(b[2 * p][0]), "=r"(b[2 * p][1]),
            "=r"(b[2 * p + 1][0]), "=r"(b[2 * p + 1][1])
          : "r"(bLane + kOff + (uint32_t)p * 1280u));
      }
#pragma unroll
      for (int mt = 0; mt < 4; ++mt)
#pragma unroll
        for (int nt = 0; nt < 4; ++nt) {
          asm volatile(
            "mma.sync.aligned.m16n8k16.row.col.f32.bf16.bf16.f32 "
            "{%0,%1,%2,%3}, {%4,%5,%6,%7}, {%8,%9}, {%0,%1,%2,%3};"
            : "+f"(acc[mt][nt][0]), "+f"(acc[mt][nt][1]),
              "+f"(acc[mt][nt][2]), "+f"(acc[mt][nt][3])
            : "r"(a[mt][0]), "r"(a[mt][1]), "r"(a[mt][2]), "r"(a[mt][3]),
              "r"(b[nt][0]), "r"(b[nt][1]));
        }
    }
  }

  // ---- epilogue: write fp32 gates (streaming, coalesced float2) ----
#pragma unroll
  for (int mt = 0; mt < 4; ++mt) {
    const int row = bm + wm + mt * 16 + gr;
#pragma unroll
    for (int nt = 0; nt < 4; ++nt) {
      const int col = bn + wn + nt * 8 + lc * 2;
      *(float2*)(g_gates + (size_t)row * G4 + col) =
          make_float2(acc[mt][nt][0], acc[mt][nt][1]);
      *(float2*)(g_gates + (size_t)(row + 8) * G4 + col) =
          make_float2(acc[mt][nt][2], acc[mt][nt][3]);
    }
  }
}

// ---------------------------------------------------------------------------
// Fused per-step tail: LSTM elementwise + LN2 + pos projection (rel out) +
// embed(rel) -> next x. One warp per ped; fast MUFU-based activations.
// h consumed in fp32 registers (LN path) -> round-3 numerics.
// ---------------------------------------------------------------------------
__global__ __launch_bounds__(256) void lstm_fused(
    const float* __restrict__ ln2_g, const float* __restrict__ ln2_b,
    const float* __restrict__ pos_W, const float* __restrict__ pos_b,
    const float* __restrict__ emb_W, const float* __restrict__ emb_b,
    const float* __restrict__ ln1_g, const float* __restrict__ ln1_b,
    float* __restrict__ rel_out, int npeds) {
  const int warp = threadIdx.x >> 5;
  const int lane = threadIdx.x & 31;
  const int ped = blockIdx.x * 8 + warp;
  if (ped >= npeds) return;

  const float* gp = g_gates + (size_t)ped * G4;
  float* cp = g_c + (size_t)ped * H;
  __nv_bfloat16* hp = g_h + (size_t)ped * H;

  float hn[8];
  float s = 0.f, ss = 0.f;
#pragma unroll
  for (int j = 0; j < 8; ++j) {
    const int ch = lane + j * 32;
    const float ig = gp[ch]           + g_bias[ch];
    const float fg = gp[256 + ch]     + g_bias[256 + ch];
    const float gg = gp[512 + ch]     + g_bias[512 + ch];
    const float og = gp[768 + ch]     + g_bias[768 + ch];
    const float cv = cp[ch];
    const float cn = sigm(fg) * cv + sigm(ig) * tanh_fast(gg);
    const float hv = sigm(og) * tanh_fast(cn);
    cp[ch] = cn;
    hp[ch] = __float2bfloat16(hv);
    hn[j] = hv;
    s += hv;
    ss += hv * hv;
  }
#pragma unroll
  for (int o = 16; o > 0; o >>= 1) {
    s += __shfl_xor_sync(0xffffffffu, s, o);
    ss += __shfl_xor_sync(0xffffffffu, ss, o);
  }
  const float mu = s * (1.f / 256.f);
  const float var = ss * (1.f / 256.f) - mu * mu;
  const float rstd = rsqrtf(var + 1e-5f);

  float d0 = 0.f, d1 = 0.f;
#pragma unroll
  for (int j = 0; j < 8; ++j) {
    const int ch = lane + j * 32;
    const float nh = (hn[j] - mu) * rstd * ln2_g[ch] + ln2_b[ch];
    d0 += nh * pos_W[ch];
    d1 += nh * pos_W[256 + ch];
  }
#pragma unroll
  for (int o = 16; o > 0; o >>= 1) {
    d0 += __shfl_xor_sync(0xffffffffu, d0, o);
    d1 += __shfl_xor_sync(0xffffffffu, d1, o);
  }
  const float r0 = sigm(d0 + pos_b[0]);
  const float r1 = sigm(d1 + pos_b[1]);
  if (lane == 0) {
    rel_out[(size_t)ped * 2 + 0] = r0;
    rel_out[(size_t)ped * 2 + 1] = r1;
  }

  // embed(rel) -> next x  (LN over 2 elems)
  const float d = 0.5f * (r0 - r1);
  const float inv = rsqrtf(d * d + 1e-5f);
  const float na =  d * inv * ln1_g[0] + ln1_b[0];
  const float nb = -d * inv * ln1_g[1] + ln1_b[1];
  __nv_bfloat16* xp = g_x + (size_t)ped * E;
#pragma unroll
  for (int q = 0; q < 2; ++q) {
    const int j = lane * 2 + q;
    const float y = na * emb_W[j * 2 + 0] + nb * emb_W[j * 2 + 1] + emb_b[j];
    xp[j] = __float2bfloat16((y > 0.f) ? y : 0.01f * y);
  }
}

// ---------------------------------------------------------------------------
extern "C" void kernel_launch(void* const* d_in, const int* in_sizes, int n_in,
                              void* d_out, int out_size) {
  const float* last_pos_rel = (const float*)d_in[1];
  const float* h0   = (const float*)d_in[2];
  const float* c0   = (const float*)d_in[3];
  const float* W_ih = (const float*)d_in[4];
  const float* W_hh = (const float*)d_in[5];
  const float* b_ih = (const float*)d_in[6];
  const float* b_hh = (const float*)d_in[7];
  const float* emb_W = (const float*)d_in[8];
  const float* emb_b = (const float*)d_in[9];
  const float* ln1_g = (const float*)d_in[10];
  const float* ln1_b = (const float*)d_in[11];
  const float* pos_W = (const float*)d_in[12];
  const float* pos_b = (const float*)d_in[13];
  const float* ln2_g = (const float*)d_in[14];
  const float* ln2_b = (const float*)d_in[15];
  float* out = (float*)d_out;

  const int npeds = in_sizes[0] / 2;  // 8192

  prep_weights<<<(G4 * KTOT + 255) / 256, 256>>>(W_ih, W_hh, b_ih, b_hh);
  init_state<<<(npeds * H + 255) / 256, 256>>>(h0, c0, npeds * H);
  embed_init<<<(npeds * E + 255) / 256, 256>>>(last_pos_rel, ln1_g, ln1_b, emb_W, emb_b, npeds);

  dim3 ggrid(G4 / 128, npeds / 128);
  for (int s = 0; s < SEQ; ++s) {
    gates_gemm<<<ggrid, 256>>>(npeds);
    lstm_fused<<<npeds / 8, 256>>>(ln2_g, ln2_b, pos_W, pos_b, emb_W, emb_b,
                                   ln1_g, ln1_b, out + (size_t)s * npeds * 2, npeds);
  }
}

// round 12
// speedup vs baseline: 1.4150x; 1.0290x over previous
#include <cuda_runtime.h>
#include <cuda_bf16.h>
#include <math.h>
#include <stdint.h>

#define NPEDS_MAX 8192
#define H 256
#define E 64
#define G4 1024   // 4*H
#define KTOT 320  // E + H
#define SEQ 30
#define KT_TILES 10  // KTOT/32

// ---- device-global scratch (no allocations allowed) ----
__device__ __align__(16) __nv_bfloat16 g_h[NPEDS_MAX * H];
__device__ float g_c[NPEDS_MAX * H];
__device__ __align__(16) __nv_bfloat16 g_x[NPEDS_MAX * E];
__device__ float g_gates[NPEDS_MAX * G4];
__device__ __align__(16) __nv_bfloat16 g_Wn[G4 * KTOT];  // [n][k] bf16, gate-major n
__device__ float g_bias[G4];

__device__ __forceinline__ float sigm(float v) { return 1.f / (1.f + __expf(-v)); }
__device__ __forceinline__ float tanh_fast(float v) {
  return 2.f / (1.f + __expf(-2.f * v)) - 1.f;
}

// ---------------------------------------------------------------------------
// Init kernels (run every graph replay -> deterministic state reset)
// ---------------------------------------------------------------------------
__global__ void prep_weights(const float* __restrict__ W_ih, const float* __restrict__ W_hh,
                             const float* __restrict__ b_ih, const float* __restrict__ b_hh) {
  int idx = blockIdx.x * blockDim.x + threadIdx.x;
  if (idx < G4 * KTOT) {
    int n = idx / KTOT, k = idx - n * KTOT;
    float w = (k < E) ? W_ih[n * E + k] : W_hh[n * H + (k - E)];
    g_Wn[idx] = __float2bfloat16(w);
  }
  if (idx < G4) g_bias[idx] = b_ih[idx] + b_hh[idx];
}

__global__ void init_state(const float* __restrict__ h0, const float* __restrict__ c0, int n) {
  int idx = blockIdx.x * blockDim.x + threadIdx.x;
  if (idx < n) { g_h[idx] = __float2bfloat16(h0[idx]); g_c[idx] = c0[idx]; }
}

// embed(p) = leaky_relu( LN_2(p) @ emb_W^T + emb_b )
__global__ void embed_init(const float* __restrict__ lpr,
                           const float* __restrict__ ln1_g, const float* __restrict__ ln1_b,
                           const float* __restrict__ emb_W, const float* __restrict__ emb_b,
                           int npeds) {
  int idx = blockIdx.x * blockDim.x + threadIdx.x;
  if (idx >= npeds * E) return;
  int ped = idx / E, j = idx - ped * E;
  float a = lpr[ped * 2 + 0], b = lpr[ped * 2 + 1];
  float d = 0.5f * (a - b);
  float inv = rsqrtf(d * d + 1e-5f);
  float na =  d * inv * ln1_g[0] + ln1_b[0];
  float nb = -d * inv * ln1_g[1] + ln1_b[1];
  float y = na * emb_W[j * 2 + 0] + nb * emb_W[j * 2 + 1] + emb_b[j];
  g_x[idx] = __float2bfloat16((y > 0.f) ? y : 0.01f * y);
}

// ---------------------------------------------------------------------------
// Per-step GEMM (bf16 MMA + ldmatrix, 3-stage cp.async pipeline, dyn smem):
//   g_gates[M,1024] = [x|h][M,320] @ Wn^T  (Wn stored [n][k])
// BM=128, BN=128, BK=32. 8 warps (2m x 4n), warp tile 64x32, mma.m16n8k16.
// 80B smem rows: LDSM-conflict-free.
// smem: A stages [3][128][20] u32 then B stages [3][128][20] u32 = 61440 B.
// ---------------------------------------------------------------------------
#define TILE_U 2560                 // 128*20 uint32 per tile
#define TILE_B 10240                // bytes per tile
#define SMEM_BYTES (6 * TILE_B)     // 61440

__global__ __launch_bounds__(256, 2) void gates_gemm(int npeds) {
  extern __shared__ __align__(16) uint32_t smem[];
  uint32_t* const As0 = smem;                 // [3][128][20]
  uint32_t* const Bs0 = smem + 3 * TILE_U;    // [3][128][20]

  const int bm = blockIdx.y * 128;
  const int bn = blockIdx.x * 128;
  const int t = threadIdx.x;
  const int warp = t >> 5;
  const int lane = t & 31;
  const int wm = (warp >> 2) * 64;
  const int wn = (warp & 3) * 32;
  const int gr = lane >> 2;   // 0..7  (store epilogue)
  const int lc = lane & 3;    // 0..3

  // ldmatrix lane addressing (stage-0 base; add stage*TILE_B at use)
  const int lg = lane >> 3;       // lane group 0..3
  const int lr = lane & 7;        // row within group
  const uint32_t aLane = (uint32_t)__cvta_generic_to_shared(
      &As0[(wm + (lg & 1) * 8 + lr) * 20 + (lg >> 1) * 4]);
  const uint32_t bLane = (uint32_t)__cvta_generic_to_shared(
      &Bs0[(wn + (lg >> 1) * 8 + lr) * 20 + (lg & 1) * 4]);

  float acc[4][4][4];
#pragma unroll
  for (int i = 0; i < 4; ++i)
#pragma unroll
    for (int j = 0; j < 4; ++j)
#pragma unroll
      for (int q = 0; q < 4; ++q) acc[i][j][q] = 0.f;

  const int mm0 = t >> 2;          // 0..63
  const int c4 = t & 3;            // 16B chunk

  auto load_tile = [&](int kt, int stage) {
    const int k0 = kt * 32;
    const __nv_bfloat16* srcA;
    int ldk, koff;
    if (k0 < E) { srcA = g_x; ldk = E; koff = k0; }
    else        { srcA = g_h; ldk = H; koff = k0 - E; }
#pragma unroll
    for (int r = 0; r < 2; ++r) {
      const int mm = mm0 + r * 64;
      const void* gA = srcA + (size_t)(bm + mm) * ldk + koff + c4 * 8;
      uint32_t dA = (uint32_t)__cvta_generic_to_shared(
          &As0[stage * TILE_U + mm * 20 + c4 * 4]);
      asm volatile("cp.async.cg.shared.global [%0], [%1], 16;\n" :: "r"(dA), "l"(gA));
      const void* gB = g_Wn + (size_t)(bn + mm) * KTOT + k0 + c4 * 8;
      uint32_t dB = (uint32_t)__cvta_generic_to_shared(
          &Bs0[stage * TILE_U + mm * 20 + c4 * 4]);
      asm volatile("cp.async.cg.shared.global [%0], [%1], 16;\n" :: "r"(dB), "l"(gB));
    }
    asm volatile("cp.async.commit_group;\n");
  };

  load_tile(0, 0);
  load_tile(1, 1);

#pragma unroll
  for (int kt = 0; kt < KT_TILES; ++kt) {
    if (kt + 1 < KT_TILES)
      asm volatile("cp.async.wait_group 1;\n" ::: "memory");
    else
      asm volatile("cp.async.wait_group 0;\n" ::: "memory");
    __syncthreads();
    if (kt + 2 < KT_TILES) load_tile(kt + 2, (kt + 2) % 3);

    const uint32_t stOff = (uint32_t)(kt % 3) * TILE_B;
#pragma unroll
    for (int ks = 0; ks < 2; ++ks) {
      const uint32_t kOff = stOff + (uint32_t)ks * 32u;
      uint32_t a[4][4], b[4][2];
#pragma unroll
      for (int mt = 0; mt < 4; ++mt) {
        asm volatile(
          "ldmatrix.sync.aligned.m8n8.x4.shared.b16 {%0,%1,%2,%3}, [%4];"
          : "=r"(a[mt][0]), "=r"(a[mt][1]), "=r"(a[mt][2]), "=r"(a[mt][3])
          : "r"(aLane + kOff + (uint32_t)mt * 1280u));   // 16 rows * 80B
      }
#pragma unroll
      for (int p = 0; p < 2; ++p) {
        asm volatile(
          "ldmatrix.sync.aligned.m8n8.x4.shared.b16 {%0,%1,%2,%3}, [%4];"
          : "=r"(b[2 * p][0]), "=r"(b[2 * p][1]),
            "=r"(b[2 * p + 1][0]), "=r"(b[2 * p + 1][1])
          : "r"(bLane + kOff + (uint32_t)p * 1280u));
      }
#pragma unroll
      for (int mt = 0; mt < 4; ++mt)
#pragma unroll
        for (int nt = 0; nt < 4; ++nt) {
          asm volatile(
            "mma.sync.aligned.m16n8k16.row.col.f32.bf16.bf16.f32 "
            "{%0,%1,%2,%3}, {%4,%5,%6,%7}, {%8,%9}, {%0,%1,%2,%3};"
            : "+f"(acc[mt][nt][0]), "+f"(acc[mt][nt][1]),
              "+f"(acc[mt][nt][2]), "+f"(acc[mt][nt][3])
            : "r"(a[mt][0]), "r"(a[mt][1]), "r"(a[mt][2]), "r"(a[mt][3]),
              "r"(b[nt][0]), "r"(b[nt][1]));
        }
    }
  }

  // ---- epilogue: write fp32 gates (streaming, coalesced float2) ----
#pragma unroll
  for (int mt = 0; mt < 4; ++mt) {
    const int row = bm + wm + mt * 16 + gr;
#pragma unroll
    for (int nt = 0; nt < 4; ++nt) {
      const int col = bn + wn + nt * 8 + lc * 2;
      *(float2*)(g_gates + (size_t)row * G4 + col) =
          make_float2(acc[mt][nt][0], acc[mt][nt][1]);
      *(float2*)(g_gates + (size_t)(row + 8) * G4 + col) =
          make_float2(acc[mt][nt][2], acc[mt][nt][3]);
    }
  }
}

// ---------------------------------------------------------------------------
// Fused per-step tail: LSTM elementwise + LN2 + pos projection (rel out) +
// embed(rel) -> next x. One warp per ped; fast MUFU-based activations.
// ---------------------------------------------------------------------------
__global__ __launch_bounds__(256) void lstm_fused(
    const float* __restrict__ ln2_g, const float* __restrict__ ln2_b,
    const float* __restrict__ pos_W, const float* __restrict__ pos_b,
    const float* __restrict__ emb_W, const float* __restrict__ emb_b,
    const float* __restrict__ ln1_g, const float* __restrict__ ln1_b,
    float* __restrict__ rel_out, int npeds) {
  const int warp = threadIdx.x >> 5;
  const int lane = threadIdx.x & 31;
  const int ped = blockIdx.x * 8 + warp;
  if (ped >= npeds) return;

  const float* gp = g_gates + (size_t)ped * G4;
  float* cp = g_c + (size_t)ped * H;
  __nv_bfloat16* hp = g_h + (size_t)ped * H;

  float hn[8];
  float s = 0.f, ss = 0.f;
#pragma unroll
  for (int j = 0; j < 8; ++j) {
    const int ch = lane + j * 32;
    const float ig = gp[ch]           + g_bias[ch];
    const float fg = gp[256 + ch]     + g_bias[256 + ch];
    const float gg = gp[512 + ch]     + g_bias[512 + ch];
    const float og = gp[768 + ch]     + g_bias[768 + ch];
    const float cv = cp[ch];
    const float cn = sigm(fg) * cv + sigm(ig) * tanh_fast(gg);
    const float hv = sigm(og) * tanh_fast(cn);
    cp[ch] = cn;
    hp[ch] = __float2bfloat16(hv);
    hn[j] = hv;
    s += hv;
    ss += hv * hv;
  }
#pragma unroll
  for (int o = 16; o > 0; o >>= 1) {
    s += __shfl_xor_sync(0xffffffffu, s, o);
    ss += __shfl_xor_sync(0xffffffffu, ss, o);
  }
  const float mu = s * (1.f / 256.f);
  const float var = ss * (1.f / 256.f) - mu * mu;
  const float rstd = rsqrtf(var + 1e-5f);

  float d0 = 0.f, d1 = 0.f;
#pragma unroll
  for (int j = 0; j < 8; ++j) {
    const int ch = lane + j * 32;
    const float nh = (hn[j] - mu) * rstd * ln2_g[ch] + ln2_b[ch];
    d0 += nh * pos_W[ch];
    d1 += nh * pos_W[256 + ch];
  }
#pragma unroll
  for (int o = 16; o > 0; o >>= 1) {
    d0 += __shfl_xor_sync(0xffffffffu, d0, o);
    d1 += __shfl_xor_sync(0xffffffffu, d1, o);
  }
  const float r0 = sigm(d0 + pos_b[0]);
  const float r1 = sigm(d1 + pos_b[1]);
  if (lane == 0) {
    rel_out[(size_t)ped * 2 + 0] = r0;
    rel_out[(size_t)ped * 2 + 1] = r1;
  }

  // embed(rel) -> next x  (LN over 2 elems)
  const float d = 0.5f * (r0 - r1);
  const float inv = rsqrtf(d * d + 1e-5f);
  const float na =  d * inv * ln1_g[0] + ln1_b[0];
  const float nb = -d * inv * ln1_g[1] + ln1_b[1];
  __nv_bfloat16* xp = g_x + (size_t)ped * E;
#pragma unroll
  for (int q = 0; q < 2; ++q) {
    const int j = lane * 2 + q;
    const float y = na * emb_W[j * 2 + 0] + nb * emb_W[j * 2 + 1] + emb_b[j];
    xp[j] = __float2bfloat16((y > 0.f) ? y : 0.01f * y);
  }
}

// ---------------------------------------------------------------------------
extern "C" void kernel_launch(void* const* d_in, const int* in_sizes, int n_in,
                              void* d_out, int out_size) {
  const float* last_pos_rel = (const float*)d_in[1];
  const float* h0   = (const float*)d_in[2];
  const float* c0   = (const float*)d_in[3];
  const float* W_ih = (const float*)d_in[4];
  const float* W_hh = (const float*)d_in[5];
  const float* b_ih = (const float*)d_in[6];
  const float* b_hh = (const float*)d_in[7];
  const float* emb_W = (const float*)d_in[8];
  const float* emb_b = (const float*)d_in[9];
  const float* ln1_g = (const float*)d_in[10];
  const float* ln1_b = (const float*)d_in[11];
  const float* pos_W = (const float*)d_in[12];
  const float* pos_b = (const float*)d_in[13];
  const float* ln2_g = (const float*)d_in[14];
  const float* ln2_b = (const float*)d_in[15];
  float* out = (float*)d_out;

  const int npeds = in_sizes[0] / 2;  // 8192

  static int smem_set = 0;
  if (!smem_set) {
    cudaFuncSetAttribute(gates_gemm, cudaFuncAttributeMaxDynamicSharedMemorySize,
                         SMEM_BYTES);
    smem_set = 1;
  }

  prep_weights<<<(G4 * KTOT + 255) / 256, 256>>>(W_ih, W_hh, b_ih, b_hh);
  init_state<<<(npeds * H + 255) / 256, 256>>>(h0, c0, npeds * H);
  embed_init<<<(npeds * E + 255) / 256, 256>>>(last_pos_rel, ln1_g, ln1_b, emb_W, emb_b, npeds);

  dim3 ggrid(G4 / 128, npeds / 128);
  for (int s = 0; s < SEQ; ++s) {
    gates_gemm<<<ggrid, 256, SMEM_BYTES>>>(npeds);
    lstm_fused<<<npeds / 8, 256>>>(ln2_g, ln2_b, pos_W, pos_b, emb_W, emb_b,
                                   ln1_g, ln1_b, out + (size_t)s * npeds * 2, npeds);
  }
}

// round 13
// speedup vs baseline: 1.4719x; 1.0402x over previous
#include <cuda_runtime.h>
#include <cuda_bf16.h>
#include <cuda_fp16.h>
#include <math.h>
#include <stdint.h>

#define NPEDS_MAX 8192
#define H 256
#define E 64
#define G4 1024   // 4*H
#define KTOT 320  // E + H
#define SEQ 30
#define KT_TILES 10  // KTOT/32

// ---- device-global scratch (no allocations allowed) ----
__device__ __align__(16) __nv_bfloat16 g_h[NPEDS_MAX * H];
__device__ __align__(16) float g_c[NPEDS_MAX * H];
__device__ __align__(16) __nv_bfloat16 g_x[NPEDS_MAX * E];
__device__ __align__(16) __half g_gates[NPEDS_MAX * G4];   // fp16 gates
__device__ __align__(16) __nv_bfloat16 g_Wn[G4 * KTOT];    // [n][k] bf16
__device__ __align__(16) float g_bias[G4];

__device__ __forceinline__ float sigm(float v) { return 1.f / (1.f + __expf(-v)); }
__device__ __forceinline__ float tanh_fast(float v) {
  return 2.f / (1.f + __expf(-2.f * v)) - 1.f;
}

// ---------------------------------------------------------------------------
// Init kernels (run every graph replay -> deterministic state reset)
// ---------------------------------------------------------------------------
__global__ void prep_weights(const float* __restrict__ W_ih, const float* __restrict__ W_hh,
                             const float* __restrict__ b_ih, const float* __restrict__ b_hh) {
  int idx = blockIdx.x * blockDim.x + threadIdx.x;
  if (idx < G4 * KTOT) {
    int n = idx / KTOT, k = idx - n * KTOT;
    float w = (k < E) ? W_ih[n * E + k] : W_hh[n * H + (k - E)];
    g_Wn[idx] = __float2bfloat16(w);
  }
  if (idx < G4) g_bias[idx] = b_ih[idx] + b_hh[idx];
}

__global__ void init_state(const float* __restrict__ h0, const float* __restrict__ c0, int n) {
  int idx = blockIdx.x * blockDim.x + threadIdx.x;
  if (idx < n) { g_h[idx] = __float2bfloat16(h0[idx]); g_c[idx] = c0[idx]; }
}

// embed(p) = leaky_relu( LN_2(p) @ emb_W^T + emb_b )
__global__ void embed_init(const float* __restrict__ lpr,
                           const float* __restrict__ ln1_g, const float* __restrict__ ln1_b,
                           const float* __restrict__ emb_W, const float* __restrict__ emb_b,
                           int npeds) {
  int idx = blockIdx.x * blockDim.x + threadIdx.x;
  if (idx >= npeds * E) return;
  int ped = idx / E, j = idx - ped * E;
  float a = lpr[ped * 2 + 0], b = lpr[ped * 2 + 1];
  float d = 0.5f * (a - b);
  float inv = rsqrtf(d * d + 1e-5f);
  float na =  d * inv * ln1_g[0] + ln1_b[0];
  float nb = -d * inv * ln1_g[1] + ln1_b[1];
  float y = na * emb_W[j * 2 + 0] + nb * emb_W[j * 2 + 1] + emb_b[j];
  g_x[idx] = __float2bfloat16((y > 0.f) ? y : 0.01f * y);
}

// ---------------------------------------------------------------------------
// Per-step GEMM (bf16 MMA + ldmatrix, 3-stage cp.async pipeline, dyn smem):
//   g_gates[M,1024](fp16) = [x|h][M,320] @ Wn^T
// BM=128, BN=128, BK=32. 8 warps (2m x 4n), warp tile 64x32, mma.m16n8k16.
// ---------------------------------------------------------------------------
#define TILE_U 2560                 // 128*20 uint32 per tile
#define TILE_B 10240                // bytes per tile
#define SMEM_BYTES (6 * TILE_B)     // 61440

__global__ __launch_bounds__(256, 2) void gates_gemm(int npeds) {
  extern __shared__ __align__(16) uint32_t smem[];
  uint32_t* const As0 = smem;                 // [3][128][20]
  uint32_t* const Bs0 = smem + 3 * TILE_U;    // [3][128][20]

  const int bm = blockIdx.y * 128;
  const int bn = blockIdx.x * 128;
  const int t = threadIdx.x;
  const int warp = t >> 5;
  const int lane = t & 31;
  const int wm = (warp >> 2) * 64;
  const int wn = (warp & 3) * 32;
  const int gr = lane >> 2;   // 0..7  (store epilogue)
  const int lc = lane & 3;    // 0..3

  const int lg = lane >> 3;       // lane group 0..3
  const int lr = lane & 7;        // row within group
  const uint32_t aLane = (uint32_t)__cvta_generic_to_shared(
      &As0[(wm + (lg & 1) * 8 + lr) * 20 + (lg >> 1) * 4]);
  const uint32_t bLane = (uint32_t)__cvta_generic_to_shared(
      &Bs0[(wn + (lg >> 1) * 8 + lr) * 20 + (lg & 1) * 4]);

  float acc[4][4][4];
#pragma unroll
  for (int i = 0; i < 4; ++i)
#pragma unroll
    for (int j = 0; j < 4; ++j)
#pragma unroll
      for (int q = 0; q < 4; ++q) acc[i][j][q] = 0.f;

  const int mm0 = t >> 2;          // 0..63
  const int c4 = t & 3;            // 16B chunk

  auto load_tile = [&](int kt, int stage) {
    const int k0 = kt * 32;
    const __nv_bfloat16* srcA;
    int ldk, koff;
    if (k0 < E) { srcA = g_x; ldk = E; koff = k0; }
    else        { srcA = g_h; ldk = H; koff = k0 - E; }
#pragma unroll
    for (int r = 0; r < 2; ++r) {
      const int mm = mm0 + r * 64;
      const void* gA = srcA + (size_t)(bm + mm) * ldk + koff + c4 * 8;
      uint32_t dA = (uint32_t)__cvta_generic_to_shared(
          &As0[stage * TILE_U + mm * 20 + c4 * 4]);
      asm volatile("cp.async.cg.shared.global [%0], [%1], 16;\n" :: "r"(dA), "l"(gA));
      const void* gB = g_Wn + (size_t)(bn + mm) * KTOT + k0 + c4 * 8;
      uint32_t dB = (uint32_t)__cvta_generic_to_shared(
          &Bs0[stage * TILE_U + mm * 20 + c4 * 4]);
      asm volatile("cp.async.cg.shared.global [%0], [%1], 16;\n" :: "r"(dB), "l"(gB));
    }
    asm volatile("cp.async.commit_group;\n");
  };

  load_tile(0, 0);
  load_tile(1, 1);

#pragma unroll
  for (int kt = 0; kt < KT_TILES; ++kt) {
    if (kt + 1 < KT_TILES)
      asm volatile("cp.async.wait_group 1;\n" ::: "memory");
    else
      asm volatile("cp.async.wait_group 0;\n" ::: "memory");
    __syncthreads();
    if (kt + 2 < KT_TILES) load_tile(kt + 2, (kt + 2) % 3);

    const uint32_t stOff = (uint32_t)(kt % 3) * TILE_B;
#pragma unroll
    for (int ks = 0; ks < 2; ++ks) {
      const uint32_t kOff = stOff + (uint32_t)ks * 32u;
      uint32_t a[4][4], b[4][2];
#pragma unroll
      for (int mt = 0; mt < 4; ++mt) {
        asm volatile(
          "ldmatrix.sync.aligned.m8n8.x4.shared.b16 {%0,%1,%2,%3}, [%4];"
          : "=r"(a[mt][0]), "=r"(a[mt][1]), "=r"(a[mt][2]), "=r"(a[mt][3])
          : "r"(aLane + kOff + (uint32_t)mt * 1280u));
      }
#pragma unroll
      for (int p = 0; p < 2; ++p) {
        asm volatile(
          "ldmatrix.sync.aligned.m8n8.x4.shared.b16 {%0,%1,%2,%3}, [%4];"
          : "=r"(b[2 * p][0]), "=r"(b[2 * p][1]),
            "=r"(b[2 * p + 1][0]), "=r"(b[2 * p + 1][1])
          : "r"(bLane + kOff + (uint32_t)p * 1280u));
      }
#pragma unroll
      for (int mt = 0; mt < 4; ++mt)
#pragma unroll
        for (int nt = 0; nt < 4; ++nt) {
          asm volatile(
            "mma.sync.aligned.m16n8k16.row.col.f32.bf16.bf16.f32 "
            "{%0,%1,%2,%3}, {%4,%5,%6,%7}, {%8,%9}, {%0,%1,%2,%3};"
            : "+f"(acc[mt][nt][0]), "+f"(acc[mt][nt][1]),
              "+f"(acc[mt][nt][2]), "+f"(acc[mt][nt][3])
            : "r"(a[mt][0]), "r"(a[mt][1]), "r"(a[mt][2]), "r"(a[mt][3]),
              "r"(b[nt][0]), "r"(b[nt][1]));
        }
    }
  }

  // ---- epilogue: write fp16 gates (half2, coalesced) ----
#pragma unroll
  for (int mt = 0; mt < 4; ++mt) {
    const int row = bm + wm + mt * 16 + gr;
#pragma unroll
    for (int nt = 0; nt < 4; ++nt) {
      const int col = bn + wn + nt * 8 + lc * 2;
      *(__half2*)(g_gates + (size_t)row * G4 + col) =
          __floats2half2_rn(acc[mt][nt][0], acc[mt][nt][1]);
      *(__half2*)(g_gates + (size_t)(row + 8) * G4 + col) =
          __floats2half2_rn(acc[mt][nt][2], acc[mt][nt][3]);
    }
  }
}

// ---------------------------------------------------------------------------
// Fused per-step tail: LSTM elementwise + LN2 + pos projection (rel out) +
// embed(rel) -> next x. One warp per ped; each thread owns channel PAIRS
// (ch = lane*2 + j*64) -> all warp accesses are full 128B transactions.
// ---------------------------------------------------------------------------
__global__ __launch_bounds__(256) void lstm_fused(
    const float* __restrict__ ln2_g, const float* __restrict__ ln2_b,
    const float* __restrict__ pos_W, const float* __restrict__ pos_b,
    const float* __restrict__ emb_W, const float* __restrict__ emb_b,
    const float* __restrict__ ln1_g, const float* __restrict__ ln1_b,
    float* __restrict__ rel_out, int npeds) {
  const int warp = threadIdx.x >> 5;
  const int lane = threadIdx.x & 31;
  const int ped = blockIdx.x * 8 + warp;
  if (ped >= npeds) return;

  const __half2* gp2 = (const __half2*)g_gates + (size_t)ped * (G4 / 2);
  float* cp = g_c + (size_t)ped * H;
  __nv_bfloat16* hp = g_h + (size_t)ped * H;

  float hn[8];
  float s = 0.f, ss = 0.f;
#pragma unroll
  for (int j = 0; j < 4; ++j) {
    const int p2 = lane + j * 32;          // half2 index within a gate block
    const int ch = p2 * 2;                 // even channel
    const float2 gi = __half22float2(gp2[p2]);
    const float2 gf = __half22float2(gp2[128 + p2]);
    const float2 gg = __half22float2(gp2[256 + p2]);
    const float2 go = __half22float2(gp2[384 + p2]);
    const float2 bi = *(const float2*)&g_bias[ch];
    const float2 bf = *(const float2*)&g_bias[256 + ch];
    const float2 bg = *(const float2*)&g_bias[512 + ch];
    const float2 bo = *(const float2*)&g_bias[768 + ch];
    const float2 cv = *(const float2*)&cp[ch];

    const float cn0 = sigm(gf.x + bf.x) * cv.x + sigm(gi.x + bi.x) * tanh_fast(gg.x + bg.x);
    const float cn1 = sigm(gf.y + bf.y) * cv.y + sigm(gi.y + bi.y) * tanh_fast(gg.y + bg.y);
    const float hv0 = sigm(go.x + bo.x) * tanh_fast(cn0);
    const float hv1 = sigm(go.y + bo.y) * tanh_fast(cn1);
    *(float2*)&cp[ch] = make_float2(cn0, cn1);
    *(__nv_bfloat162*)&hp[ch] = __floats2bfloat162_rn(hv0, hv1);
    hn[j * 2] = hv0; hn[j * 2 + 1] = hv1;
    s += hv0 + hv1;
    ss += hv0 * hv0 + hv1 * hv1;
  }
#pragma unroll
  for (int o = 16; o > 0; o >>= 1) {
    s += __shfl_xor_sync(0xffffffffu, s, o);
    ss += __shfl_xor_sync(0xffffffffu, ss, o);
  }
  const float mu = s * (1.f / 256.f);
  const float var = ss * (1.f / 256.f) - mu * mu;
  const float rstd = rsqrtf(var + 1e-5f);

  float d0 = 0.f, d1 = 0.f;
#pragma unroll
  for (int j = 0; j < 4; ++j) {
    const int ch = lane * 2 + j * 64;
    const float2 g2 = *(const float2*)&ln2_g[ch];
    const float2 b2 = *(const float2*)&ln2_b[ch];
    const float2 w0 = *(const float2*)&pos_W[ch];
    const float2 w1 = *(const float2*)&pos_W[256 + ch];
    const float nh0 = (hn[j * 2] - mu) * rstd * g2.x + b2.x;
    const float nh1 = (hn[j * 2 + 1] - mu) * rstd * g2.y + b2.y;
    d0 += nh0 * w0.x + nh1 * w0.y;
    d1 += nh0 * w1.x + nh1 * w1.y;
  }
#pragma unroll
  for (int o = 16; o > 0; o >>= 1) {
    d0 += __shfl_xor_sync(0xffffffffu, d0, o);
    d1 += __shfl_xor_sync(0xffffffffu, d1, o);
  }
  const float r0 = sigm(d0 + pos_b[0]);
  const float r1 = sigm(d1 + pos_b[1]);
  if (lane == 0) {
    rel_out[(size_t)ped * 2 + 0] = r0;
    rel_out[(size_t)ped * 2 + 1] = r1;
  }

  // embed(rel) -> next x  (LN over 2 elems)
  const float d = 0.5f * (r0 - r1);
  const float inv = rsqrtf(d * d + 1e-5f);
  const float na =  d * inv * ln1_g[0] + ln1_b[0];
  const float nb = -d * inv * ln1_g[1] + ln1_b[1];
  __nv_bfloat16* xp = g_x + (size_t)ped * E;
#pragma unroll
  for (int q = 0; q < 2; ++q) {
    const int j = lane * 2 + q;
    const float y = na * emb_W[j * 2 + 0] + nb * emb_W[j * 2 + 1] + emb_b[j];
    xp[j] = __float2bfloat16((y > 0.f) ? y : 0.01f * y);
  }
}

// ---------------------------------------------------------------------------
extern "C" void kernel_launch(void* const* d_in, const int* in_sizes, int n_in,
                              void* d_out, int out_size) {
  const float* last_pos_rel = (const float*)d_in[1];
  const float* h0   = (const float*)d_in[2];
  const float* c0   = (const float*)d_in[3];
  const float* W_ih = (const float*)d_in[4];
  const float* W_hh = (const float*)d_in[5];
  const float* b_ih = (const float*)d_in[6];
  const float* b_hh = (const float*)d_in[7];
  const float* emb_W = (const float*)d_in[8];
  const float* emb_b = (const float*)d_in[9];
  const float* ln1_g = (const float*)d_in[10];
  const float* ln1_b = (const float*)d_in[11];
  const float* pos_W = (const float*)d_in[12];
  const float* pos_b = (const float*)d_in[13];
  const float* ln2_g = (const float*)d_in[14];
  const float* ln2_b = (const float*)d_in[15];
  float* out = (float*)d_out;

  const int npeds = in_sizes[0] / 2;  // 8192

  static int smem_set = 0;
  if (!smem_set) {
    cudaFuncSetAttribute(gates_gemm, cudaFuncAttributeMaxDynamicSharedMemorySize,
                         SMEM_BYTES);
    smem_set = 1;
  }

  prep_weights<<<(G4 * KTOT + 255) / 256, 256>>>(W_ih, W_hh, b_ih, b_hh);
  init_state<<<(npeds * H + 255) / 256, 256>>>(h0, c0, npeds * H);
  embed_init<<<(npeds * E + 255) / 256, 256>>>(last_pos_rel, ln1_g, ln1_b, emb_W, emb_b, npeds);

  dim3 ggrid(G4 / 128, npeds / 128);
  for (int s = 0; s < SEQ; ++s) {
    gates_gemm<<<ggrid, 256, SMEM_BYTES>>>(npeds);
    lstm_fused<<<npeds / 8, 256>>>(ln2_g, ln2_b, pos_W, pos_b, emb_W, emb_b,
                                   ln1_g, ln1_b, out + (size_t)s * npeds * 2, npeds);
  }
}

// round 14
// speedup vs baseline: 1.5497x; 1.0529x over previous
#include <cuda_runtime.h>
#include <cuda_bf16.h>
#include <cuda_fp16.h>
#include <math.h>
#include <stdint.h>

#define NPEDS_MAX 8192
#define H 256
#define E 64
#define G4 1024   // 4*H
#define KTOT 320  // E + H
#define SEQ 30
#define KT_TILES 10  // KTOT/32

// ---- device-global scratch (no allocations allowed) ----
__device__ __align__(16) __nv_bfloat16 g_h[NPEDS_MAX * H];
__device__ __align__(16) float g_c[NPEDS_MAX * H];
__device__ __align__(16) __nv_bfloat16 g_x[NPEDS_MAX * E];
__device__ __align__(16) __half g_gates[NPEDS_MAX * G4];   // fp16 gates
__device__ __align__(16) __nv_bfloat16 g_Wn[G4 * KTOT];    // [n][k] bf16
__device__ __align__(16) float g_bias[G4];

__device__ __forceinline__ float sigm(float v) { return 1.f / (1.f + __expf(-v)); }
__device__ __forceinline__ float tanh_fast(float v) {
  return 2.f / (1.f + __expf(-2.f * v)) - 1.f;
}
// HW tanh (MUFU.TANH) — used ONLY on the output path (no c-recurrence).
__device__ __forceinline__ float tanh_ap(float x) {
  float y;
  asm("tanh.approx.f32 %0, %1;" : "=f"(y) : "f"(x));
  return y;
}
__device__ __forceinline__ float sigm_ap(float v) {
  return fmaf(tanh_ap(0.5f * v), 0.5f, 0.5f);
}

// ---------------------------------------------------------------------------
// Init kernels (run every graph replay -> deterministic state reset)
// ---------------------------------------------------------------------------
__global__ void prep_weights(const float* __restrict__ W_ih, const float* __restrict__ W_hh,
                             const float* __restrict__ b_ih, const float* __restrict__ b_hh) {
  int idx = blockIdx.x * blockDim.x + threadIdx.x;
  if (idx < G4 * KTOT) {
    int n = idx / KTOT, k = idx - n * KTOT;
    float w = (k < E) ? W_ih[n * E + k] : W_hh[n * H + (k - E)];
    g_Wn[idx] = __float2bfloat16(w);
  }
  if (idx < G4) g_bias[idx] = b_ih[idx] + b_hh[idx];
}

__global__ void init_state(const float* __restrict__ h0, const float* __restrict__ c0, int n) {
  int idx = blockIdx.x * blockDim.x + threadIdx.x;
  if (idx < n) { g_h[idx] = __float2bfloat16(h0[idx]); g_c[idx] = c0[idx]; }
}

// embed(p) = leaky_relu( LN_2(p) @ emb_W^T + emb_b )
__global__ void embed_init(const float* __restrict__ lpr,
                           const float* __restrict__ ln1_g, const float* __restrict__ ln1_b,
                           const float* __restrict__ emb_W, const float* __restrict__ emb_b,
                           int npeds) {
  int idx = blockIdx.x * blockDim.x + threadIdx.x;
  if (idx >= npeds * E) return;
  int ped = idx / E, j = idx - ped * E;
  float a = lpr[ped * 2 + 0], b = lpr[ped * 2 + 1];
  float d = 0.5f * (a - b);
  float inv = rsqrtf(d * d + 1e-5f);
  float na =  d * inv * ln1_g[0] + ln1_b[0];
  float nb = -d * inv * ln1_g[1] + ln1_b[1];
  float y = na * emb_W[j * 2 + 0] + nb * emb_W[j * 2 + 1] + emb_b[j];
  g_x[idx] = __float2bfloat16((y > 0.f) ? y : 0.01f * y);
}

// ---------------------------------------------------------------------------
// Per-step GEMM (bf16 MMA + ldmatrix, 4-stage cp.async pipeline, dyn smem):
//   g_gates[M,1024](fp16) = [x|h][M,320] @ Wn^T
// BM=128, BN=128, BK=32. 8 warps (2m x 4n), warp tile 64x32, mma.m16n8k16.
// ---------------------------------------------------------------------------
#define TILE_U 2560                 // 128*20 uint32 per tile
#define TILE_B 10240                // bytes per tile
#define SMEM_BYTES (8 * TILE_B)     // 4 stages x (A,B) = 81920

__global__ __launch_bounds__(256, 2) void gates_gemm(int npeds) {
  extern __shared__ __align__(16) uint32_t smem[];
  uint32_t* const As0 = smem;                 // [4][128][20]
  uint32_t* const Bs0 = smem + 4 * TILE_U;    // [4][128][20]

  const int bm = blockIdx.y * 128;
  const int bn = blockIdx.x * 128;
  const int t = threadIdx.x;
  const int warp = t >> 5;
  const int lane = t & 31;
  const int wm = (warp >> 2) * 64;
  const int wn = (warp & 3) * 32;
  const int gr = lane >> 2;   // 0..7  (store epilogue)
  const int lc = lane & 3;    // 0..3

  const int lg = lane >> 3;       // lane group 0..3
  const int lr = lane & 7;        // row within group
  const uint32_t aLane = (uint32_t)__cvta_generic_to_shared(
      &As0[(wm + (lg & 1) * 8 + lr) * 20 + (lg >> 1) * 4]);
  const uint32_t bLane = (uint32_t)__cvta_generic_to_shared(
      &Bs0[(wn + (lg >> 1) * 8 + lr) * 20 + (lg & 1) * 4]);

  float acc[4][4][4];
#pragma unroll
  for (int i = 0; i < 4; ++i)
#pragma unroll
    for (int j = 0; j < 4; ++j)
#pragma unroll
      for (int q = 0; q < 4; ++q) acc[i][j][q] = 0.f;

  const int mm0 = t >> 2;          // 0..63
  const int c4 = t & 3;            // 16B chunk

  auto load_tile = [&](int kt, int stage) {
    const int k0 = kt * 32;
    const __nv_bfloat16* srcA;
    int ldk, koff;
    if (k0 < E) { srcA = g_x; ldk = E; koff = k0; }
    else        { srcA = g_h; ldk = H; koff = k0 - E; }
#pragma unroll
    for (int r = 0; r < 2; ++r) {
      const int mm = mm0 + r * 64;
      const void* gA = srcA + (size_t)(bm + mm) * ldk + koff + c4 * 8;
      uint32_t dA = (uint32_t)__cvta_generic_to_shared(
          &As0[stage * TILE_U + mm * 20 + c4 * 4]);
      asm volatile("cp.async.cg.shared.global [%0], [%1], 16;\n" :: "r"(dA), "l"(gA));
      const void* gB = g_Wn + (size_t)(bn + mm) * KTOT + k0 + c4 * 8;
      uint32_t dB = (uint32_t)__cvta_generic_to_shared(
          &Bs0[stage * TILE_U + mm * 20 + c4 * 4]);
      asm volatile("cp.async.cg.shared.global [%0], [%1], 16;\n" :: "r"(dB), "l"(gB));
    }
    asm volatile("cp.async.commit_group;\n");
  };

  load_tile(0, 0);
  load_tile(1, 1);
  load_tile(2, 2);

#pragma unroll
  for (int kt = 0; kt < KT_TILES; ++kt) {
    if (kt < KT_TILES - 2)
      asm volatile("cp.async.wait_group 2;\n" ::: "memory");
    else if (kt == KT_TILES - 2)
      asm volatile("cp.async.wait_group 1;\n" ::: "memory");
    else
      asm volatile("cp.async.wait_group 0;\n" ::: "memory");
    __syncthreads();
    if (kt + 3 < KT_TILES) load_tile(kt + 3, (kt + 3) & 3);

    const uint32_t stOff = (uint32_t)(kt & 3) * TILE_B;
#pragma unroll
    for (int ks = 0; ks < 2; ++ks) {
      const uint32_t kOff = stOff + (uint32_t)ks * 32u;
      uint32_t a[4][4], b[4][2];
#pragma unroll
      for (int mt = 0; mt < 4; ++mt) {
        asm volatile(
          "ldmatrix.sync.aligned.m8n8.x4.shared.b16 {%0,%1,%2,%3}, [%4];"
          : "=r"(a[mt][0]), "=r"(a[mt][1]), "=r"(a[mt][2]), "=r"(a[mt][3])
          : "r"(aLane + kOff + (uint32_t)mt * 1280u));
      }
#pragma unroll
      for (int p = 0; p < 2; ++p) {
        asm volatile(
          "ldmatrix.sync.aligned.m8n8.x4.shared.b16 {%0,%1,%2,%3}, [%4];"
          : "=r"(b[2 * p][0]), "=r"(b[2 * p][1]),
            "=r"(b[2 * p + 1][0]), "=r"(b[2 * p + 1][1])
          : "r"(bLane + kOff + (uint32_t)p * 1280u));
      }
#pragma unroll
      for (int mt = 0; mt < 4; ++mt)
#pragma unroll
        for (int nt = 0; nt < 4; ++nt) {
          asm volatile(
            "mma.sync.aligned.m16n8k16.row.col.f32.bf16.bf16.f32 "
            "{%0,%1,%2,%3}, {%4,%5,%6,%7}, {%8,%9}, {%0,%1,%2,%3};"
            : "+f"(acc[mt][nt][0]), "+f"(acc[mt][nt][1]),
              "+f"(acc[mt][nt][2]), "+f"(acc[mt][nt][3])
            : "r"(a[mt][0]), "r"(a[mt][1]), "r"(a[mt][2]), "r"(a[mt][3]),
              "r"(b[nt][0]), "r"(b[nt][1]));
        }
    }
  }

  // ---- epilogue: write fp16 gates (half2, coalesced) ----
#pragma unroll
  for (int mt = 0; mt < 4; ++mt) {
    const int row = bm + wm + mt * 16 + gr;
#pragma unroll
    for (int nt = 0; nt < 4; ++nt) {
      const int col = bn + wn + nt * 8 + lc * 2;
      *(__half2*)(g_gates + (size_t)row * G4 + col) =
          __floats2half2_rn(acc[mt][nt][0], acc[mt][nt][1]);
      *(__half2*)(g_gates + (size_t)(row + 8) * G4 + col) =
          __floats2half2_rn(acc[mt][nt][2], acc[mt][nt][3]);
    }
  }
}

// ---------------------------------------------------------------------------
// Fused per-step tail: LSTM elementwise + LN2 + pos projection (rel out) +
// embed(rel) -> next x. Channel-pair lanes -> all accesses 128B/warp.
// i/f/g gates: exact __expf path (c recurrence stays clean).
// o gate + tanh(cn): MUFU.TANH (output path, per-step independent error).
// ---------------------------------------------------------------------------
__global__ __launch_bounds__(256) void lstm_fused(
    const float* __restrict__ ln2_g, const float* __restrict__ ln2_b,
    const float* __restrict__ pos_W, const float* __restrict__ pos_b,
    const float* __restrict__ emb_W, const float* __restrict__ emb_b,
    const float* __restrict__ ln1_g, const float* __restrict__ ln1_b,
    float* __restrict__ rel_out, int npeds) {
  const int warp = threadIdx.x >> 5;
  const int lane = threadIdx.x & 31;
  const int ped = blockIdx.x * 8 + warp;
  if (ped >= npeds) return;

  const __half2* gp2 = (const __half2*)g_gates + (size_t)ped * (G4 / 2);
  float* cp = g_c + (size_t)ped * H;
  __nv_bfloat16* hp = g_h + (size_t)ped * H;

  float hn[8];
  float s = 0.f, ss = 0.f;
#pragma unroll
  for (int j = 0; j < 4; ++j) {
    const int p2 = lane + j * 32;          // half2 index within a gate block
    const int ch = p2 * 2;                 // even channel
    const float2 gi = __half22float2(gp2[p2]);
    const float2 gf = __half22float2(gp2[128 + p2]);
    const float2 gg = __half22float2(gp2[256 + p2]);
    const float2 go = __half22float2(gp2[384 + p2]);
    const float2 bi = *(const float2*)&g_bias[ch];
    const float2 bf = *(const float2*)&g_bias[256 + ch];
    const float2 bg = *(const float2*)&g_bias[512 + ch];
    const float2 bo = *(const float2*)&g_bias[768 + ch];
    const float2 cv = *(const float2*)&cp[ch];

    const float cn0 = sigm(gf.x + bf.x) * cv.x + sigm(gi.x + bi.x) * tanh_fast(gg.x + bg.x);
    const float cn1 = sigm(gf.y + bf.y) * cv.y + sigm(gi.y + bi.y) * tanh_fast(gg.y + bg.y);
    const float hv0 = sigm_ap(go.x + bo.x) * tanh_ap(cn0);
    const float hv1 = sigm_ap(go.y + bo.y) * tanh_ap(cn1);
    *(float2*)&cp[ch] = make_float2(cn0, cn1);
    *(__nv_bfloat162*)&hp[ch] = __floats2bfloat162_rn(hv0, hv1);
    hn[j * 2] = hv0; hn[j * 2 + 1] = hv1;
    s += hv0 + hv1;
    ss += hv0 * hv0 + hv1 * hv1;
  }
#pragma unroll
  for (int o = 16; o > 0; o >>= 1) {
    s += __shfl_xor_sync(0xffffffffu, s, o);
    ss += __shfl_xor_sync(0xffffffffu, ss, o);
  }
  const float mu = s * (1.f / 256.f);
  const float var = ss * (1.f / 256.f) - mu * mu;
  const float rstd = rsqrtf(var + 1e-5f);

  float d0 = 0.f, d1 = 0.f;
#pragma unroll
  for (int j = 0; j < 4; ++j) {
    const int ch = lane * 2 + j * 64;
    const float2 g2 = *(const float2*)&ln2_g[ch];
    const float2 b2 = *(const float2*)&ln2_b[ch];
    const float2 w0 = *(const float2*)&pos_W[ch];
    const float2 w1 = *(const float2*)&pos_W[256 + ch];
    const float nh0 = (hn[j * 2] - mu) * rstd * g2.x + b2.x;
    const float nh1 = (hn[j * 2 + 1] - mu) * rstd * g2.y + b2.y;
    d0 += nh0 * w0.x + nh1 * w0.y;
    d1 += nh0 * w1.x + nh1 * w1.y;
  }
#pragma unroll
  for (int o = 16; o > 0; o >>= 1) {
    d0 += __shfl_xor_sync(0xffffffffu, d0, o);
    d1 += __shfl_xor_sync(0xffffffffu, d1, o);
  }
  const float r0 = sigm(d0 + pos_b[0]);
  const float r1 = sigm(d1 + pos_b[1]);
  if (lane == 0) {
    rel_out[(size_t)ped * 2 + 0] = r0;
    rel_out[(size_t)ped * 2 + 1] = r1;
  }

  // embed(rel) -> next x  (LN over 2 elems)
  const float d = 0.5f * (r0 - r1);
  const float inv = rsqrtf(d * d + 1e-5f);
  const float na =  d * inv * ln1_g[0] + ln1_b[0];
  const float nb = -d * inv * ln1_g[1] + ln1_b[1];
  __nv_bfloat16* xp = g_x + (size_t)ped * E;
#pragma unroll
  for (int q = 0; q < 2; ++q) {
    const int j = lane * 2 + q;
    const float y = na * emb_W[j * 2 + 0] + nb * emb_W[j * 2 + 1] + emb_b[j];
    xp[j] = __float2bfloat16((y > 0.f) ? y : 0.01f * y);
  }
}

// ---------------------------------------------------------------------------
extern "C" void kernel_launch(void* const* d_in, const int* in_sizes, int n_in,
                              void* d_out, int out_size) {
  const float* last_pos_rel = (const float*)d_in[1];
  const float* h0   = (const float*)d_in[2];
  const float* c0   = (const float*)d_in[3];
  const float* W_ih = (const float*)d_in[4];
  const float* W_hh = (const float*)d_in[5];
  const float* b_ih = (const float*)d_in[6];
  const float* b_hh = (const float*)d_in[7];
  const float* emb_W = (const float*)d_in[8];
  const float* emb_b = (const float*)d_in[9];
  const float* ln1_g = (const float*)d_in[10];
  const float* ln1_b = (const float*)d_in[11];
  const float* pos_W = (const float*)d_in[12];
  const float* pos_b = (const float*)d_in[13];
  const float* ln2_g = (const float*)d_in[14];
  const float* ln2_b = (const float*)d_in[15];
  float* out = (float*)d_out;

  const int npeds = in_sizes[0] / 2;  // 8192

  static int smem_set = 0;
  if (!smem_set) {
    cudaFuncSetAttribute(gates_gemm, cudaFuncAttributeMaxDynamicSharedMemorySize,
                         SMEM_BYTES);
    smem_set = 1;
  }

  prep_weights<<<(G4 * KTOT + 255) / 256, 256>>>(W_ih, W_hh, b_ih, b_hh);
  init_state<<<(npeds * H + 255) / 256, 256>>>(h0, c0, npeds * H);
  embed_init<<<(npeds * E + 255) / 256, 256>>>(last_pos_rel, ln1_g, ln1_b, emb_W, emb_b, npeds);

  dim3 ggrid(G4 / 128, npeds / 128);
  for (int s = 0; s < SEQ; ++s) {
    gates_gemm<<<ggrid, 256, SMEM_BYTES>>>(npeds);
    lstm_fused<<<npeds / 8, 256>>>(ln2_g, ln2_b, pos_W, pos_b, emb_W, emb_b,
                                   ln1_g, ln1_b, out + (size_t)s * npeds * 2, npeds);
  }
}

// round 15
// speedup vs baseline: 1.5523x; 1.0017x over previous
#include <cuda_runtime.h>
#include <cuda_bf16.h>
#include <cuda_fp16.h>
#include <math.h>
#include <stdint.h>

#define NPEDS_MAX 8192
#define H 256
#define E 64
#define G4 1024   // 4*H
#define KTOT 320  // E + H
#define SEQ 30
#define KT_TILES 10  // KTOT/32

// ---- device-global scratch (no allocations allowed) ----
__device__ __align__(16) __half g_h[NPEDS_MAX * H];
__device__ __align__(16) float g_c[NPEDS_MAX * H];
__device__ __align__(16) __half g_x[NPEDS_MAX * E];
__device__ __align__(16) __half g_gates[NPEDS_MAX * G4];   // fp16 gates
__device__ __align__(16) __half g_Wn[G4 * KTOT];           // [n][k] fp16
__device__ __align__(16) float g_bias[G4];

__device__ __forceinline__ float sigm(float v) { return 1.f / (1.f + __expf(-v)); }
__device__ __forceinline__ float tanh_fast(float v) {
  return 2.f / (1.f + __expf(-2.f * v)) - 1.f;
}
// HW tanh (MUFU.TANH) — used ONLY on the output path (no c-recurrence).
__device__ __forceinline__ float tanh_ap(float x) {
  float y;
  asm("tanh.approx.f32 %0, %1;" : "=f"(y) : "f"(x));
  return y;
}
__device__ __forceinline__ float sigm_ap(float v) {
  return fmaf(tanh_ap(0.5f * v), 0.5f, 0.5f);
}

// ---------------------------------------------------------------------------
// Init kernels (run every graph replay -> deterministic state reset)
// ---------------------------------------------------------------------------
__global__ void prep_weights(const float* __restrict__ W_ih, const float* __restrict__ W_hh,
                             const float* __restrict__ b_ih, const float* __restrict__ b_hh) {
  int idx = blockIdx.x * blockDim.x + threadIdx.x;
  if (idx < G4 * KTOT) {
    int n = idx / KTOT, k = idx - n * KTOT;
    float w = (k < E) ? W_ih[n * E + k] : W_hh[n * H + (k - E)];
    g_Wn[idx] = __float2half(w);
  }
  if (idx < G4) g_bias[idx] = b_ih[idx] + b_hh[idx];
}

__global__ void init_state(const float* __restrict__ h0, const float* __restrict__ c0, int n) {
  int idx = blockIdx.x * blockDim.x + threadIdx.x;
  if (idx < n) { g_h[idx] = __float2half(h0[idx]); g_c[idx] = c0[idx]; }
}

// embed(p) = leaky_relu( LN_2(p) @ emb_W^T + emb_b )
__global__ void embed_init(const float* __restrict__ lpr,
                           const float* __restrict__ ln1_g, const float* __restrict__ ln1_b,
                           const float* __restrict__ emb_W, const float* __restrict__ emb_b,
                           int npeds) {
  int idx = blockIdx.x * blockDim.x + threadIdx.x;
  if (idx >= npeds * E) return;
  int ped = idx / E, j = idx - ped * E;
  float a = lpr[ped * 2 + 0], b = lpr[ped * 2 + 1];
  float d = 0.5f * (a - b);
  float inv = rsqrtf(d * d + 1e-5f);
  float na =  d * inv * ln1_g[0] + ln1_b[0];
  float nb = -d * inv * ln1_g[1] + ln1_b[1];
  float y = na * emb_W[j * 2 + 0] + nb * emb_W[j * 2 + 1] + emb_b[j];
  g_x[idx] = __float2half((y > 0.f) ? y : 0.01f * y);
}

// ---------------------------------------------------------------------------
// Per-step GEMM (fp16 MMA, fp16 accum, ldmatrix, 4-stage cp.async, dyn smem):
//   g_gates[M,1024](fp16) = [x|h][M,320] @ Wn^T
// BM=128, BN=128, BK=32. 8 warps (2m x 4n), warp tile 64x32,
// mma.m16n8k16.f16.f16.f16.f16 (accum = packed f16x2, 32 regs).
// All 12 LDSM of a k-tile hoisted before the 32 MMAs (freed regs).
// ---------------------------------------------------------------------------
#define TILE_U 2560                 // 128*20 uint32 per tile
#define TILE_B 10240                // bytes per tile
#define SMEM_BYTES (8 * TILE_B)     // 4 stages x (A,B) = 81920

__global__ __launch_bounds__(256, 2) void gates_gemm(int npeds) {
  extern __shared__ __align__(16) uint32_t smem[];
  uint32_t* const As0 = smem;                 // [4][128][20]
  uint32_t* const Bs0 = smem + 4 * TILE_U;    // [4][128][20]

  const int bm = blockIdx.y * 128;
  const int bn = blockIdx.x * 128;
  const int t = threadIdx.x;
  const int warp = t >> 5;
  const int lane = t & 31;
  const int wm = (warp >> 2) * 64;
  const int wn = (warp & 3) * 32;
  const int gr = lane >> 2;   // 0..7  (store epilogue)
  const int lc = lane & 3;    // 0..3

  const int lg = lane >> 3;       // lane group 0..3
  const int lr = lane & 7;        // row within group
  const uint32_t aLane = (uint32_t)__cvta_generic_to_shared(
      &As0[(wm + (lg & 1) * 8 + lr) * 20 + (lg >> 1) * 4]);
  const uint32_t bLane = (uint32_t)__cvta_generic_to_shared(
      &Bs0[(wn + (lg >> 1) * 8 + lr) * 20 + (lg & 1) * 4]);

  uint32_t acc[4][4][2];          // f16x2 accumulators
#pragma unroll
  for (int i = 0; i < 4; ++i)
#pragma unroll
    for (int j = 0; j < 4; ++j) { acc[i][j][0] = 0u; acc[i][j][1] = 0u; }

  const int mm0 = t >> 2;          // 0..63
  const int c4 = t & 3;            // 16B chunk

  auto load_tile = [&](int kt, int stage) {
    const int k0 = kt * 32;
    const __half* srcA;
    int ldk, koff;
    if (k0 < E) { srcA = g_x; ldk = E; koff = k0; }
    else        { srcA = g_h; ldk = H; koff = k0 - E; }
#pragma unroll
    for (int r = 0; r < 2; ++r) {
      const int mm = mm0 + r * 64;
      const void* gA = srcA + (size_t)(bm + mm) * ldk + koff + c4 * 8;
      uint32_t dA = (uint32_t)__cvta_generic_to_shared(
          &As0[stage * TILE_U + mm * 20 + c4 * 4]);
      asm volatile("cp.async.cg.shared.global [%0], [%1], 16;\n" :: "r"(dA), "l"(gA));
      const void* gB = g_Wn + (size_t)(bn + mm) * KTOT + k0 + c4 * 8;
      uint32_t dB = (uint32_t)__cvta_generic_to_shared(
          &Bs0[stage * TILE_U + mm * 20 + c4 * 4]);
      asm volatile("cp.async.cg.shared.global [%0], [%1], 16;\n" :: "r"(dB), "l"(gB));
    }
    asm volatile("cp.async.commit_group;\n");
  };

  load_tile(0, 0);
  load_tile(1, 1);
  load_tile(2, 2);

#pragma unroll
  for (int kt = 0; kt < KT_TILES; ++kt) {
    if (kt < KT_TILES - 2)
      asm volatile("cp.async.wait_group 2;\n" ::: "memory");
    else if (kt == KT_TILES - 2)
      asm volatile("cp.async.wait_group 1;\n" ::: "memory");
    else
      asm volatile("cp.async.wait_group 0;\n" ::: "memory");
    __syncthreads();
    if (kt + 3 < KT_TILES) load_tile(kt + 3, (kt + 3) & 3);

    const uint32_t stOff = (uint32_t)(kt & 3) * TILE_B;

    // ---- hoist ALL fragment loads for both ks halves of this k-tile ----
    uint32_t a[2][4][4], b[2][4][2];
#pragma unroll
    for (int ks = 0; ks < 2; ++ks) {
      const uint32_t kOff = stOff + (uint32_t)ks * 32u;
#pragma unroll
      for (int mt = 0; mt < 4; ++mt) {
        asm volatile(
          "ldmatrix.sync.aligned.m8n8.x4.shared.b16 {%0,%1,%2,%3}, [%4];"
          : "=r"(a[ks][mt][0]), "=r"(a[ks][mt][1]),
            "=r"(a[ks][mt][2]), "=r"(a[ks][mt][3])
          : "r"(aLane + kOff + (uint32_t)mt * 1280u));
      }
#pragma unroll
      for (int p = 0; p < 2; ++p) {
        asm volatile(
          "ldmatrix.sync.aligned.m8n8.x4.shared.b16 {%0,%1,%2,%3}, [%4];"
          : "=r"(b[ks][2 * p][0]), "=r"(b[ks][2 * p][1]),
            "=r"(b[ks][2 * p + 1][0]), "=r"(b[ks][2 * p + 1][1])
          : "r"(bLane + kOff + (uint32_t)p * 1280u));
      }
    }
    // ---- 32 MMAs ----
#pragma unroll
    for (int ks = 0; ks < 2; ++ks)
#pragma unroll
      for (int mt = 0; mt < 4; ++mt)
#pragma unroll
        for (int nt = 0; nt < 4; ++nt) {
          asm volatile(
            "mma.sync.aligned.m16n8k16.row.col.f16.f16.f16.f16 "
            "{%0,%1}, {%2,%3,%4,%5}, {%6,%7}, {%0,%1};"
            : "+r"(acc[mt][nt][0]), "+r"(acc[mt][nt][1])
            : "r"(a[ks][mt][0]), "r"(a[ks][mt][1]),
              "r"(a[ks][mt][2]), "r"(a[ks][mt][3]),
              "r"(b[ks][nt][0]), "r"(b[ks][nt][1]));
        }
  }

  // ---- epilogue: accumulators ARE the fp16 gates; direct half2 stores ----
#pragma unroll
  for (int mt = 0; mt < 4; ++mt) {
    const int row = bm + wm + mt * 16 + gr;
#pragma unroll
    for (int nt = 0; nt < 4; ++nt) {
      const int col = bn + wn + nt * 8 + lc * 2;
      *(uint32_t*)(g_gates + (size_t)row * G4 + col) = acc[mt][nt][0];
      *(uint32_t*)(g_gates + (size_t)(row + 8) * G4 + col) = acc[mt][nt][1];
    }
  }
}

// ---------------------------------------------------------------------------
// Fused per-step tail: LSTM elementwise + LN2 + pos projection (rel out) +
// embed(rel) -> next x. Channel-pair lanes -> all accesses 128B/warp.
// i/f/g gates: exact __expf path (c recurrence clean); o/tanh(cn): MUFU.TANH.
// ---------------------------------------------------------------------------
__global__ __launch_bounds__(256) void lstm_fused(
    const float* __restrict__ ln2_g, const float* __restrict__ ln2_b,
    const float* __restrict__ pos_W, const float* __restrict__ pos_b,
    const float* __restrict__ emb_W, const float* __restrict__ emb_b,
    const float* __restrict__ ln1_g, const float* __restrict__ ln1_b,
    float* __restrict__ rel_out, int npeds) {
  const int warp = threadIdx.x >> 5;
  const int lane = threadIdx.x & 31;
  const int ped = blockIdx.x * 8 + warp;
  if (ped >= npeds) return;

  const __half2* gp2 = (const __half2*)g_gates + (size_t)ped * (G4 / 2);
  float* cp = g_c + (size_t)ped * H;
  __half* hp = g_h + (size_t)ped * H;

  float hn[8];
  float s = 0.f, ss = 0.f;
#pragma unroll
  for (int j = 0; j < 4; ++j) {
    const int p2 = lane + j * 32;          // half2 index within a gate block
    const int ch = p2 * 2;                 // even channel
    const float2 gi = __half22float2(gp2[p2]);
    const float2 gf = __half22float2(gp2[128 + p2]);
    const float2 gg = __half22float2(gp2[256 + p2]);
    const float2 go = __half22float2(gp2[384 + p2]);
    const float2 bi = *(const float2*)&g_bias[ch];
    const float2 bf = *(const float2*)&g_bias[256 + ch];
    const float2 bg = *(const float2*)&g_bias[512 + ch];
    const float2 bo = *(const float2*)&g_bias[768 + ch];
    const float2 cv = *(const float2*)&cp[ch];

    const float cn0 = sigm(gf.x + bf.x) * cv.x + sigm(gi.x + bi.x) * tanh_fast(gg.x + bg.x);
    const float cn1 = sigm(gf.y + bf.y) * cv.y + sigm(gi.y + bi.y) * tanh_fast(gg.y + bg.y);
    const float hv0 = sigm_ap(go.x + bo.x) * tanh_ap(cn0);
    const float hv1 = sigm_ap(go.y + bo.y) * tanh_ap(cn1);
    *(float2*)&cp[ch] = make_float2(cn0, cn1);
    *(__half2*)&hp[ch] = __floats2half2_rn(hv0, hv1);
    hn[j * 2] = hv0; hn[j * 2 + 1] = hv1;
    s += hv0 + hv1;
    ss += hv0 * hv0 + hv1 * hv1;
  }
#pragma unroll
  for (int o = 16; o > 0; o >>= 1) {
    s += __shfl_xor_sync(0xffffffffu, s, o);
    ss += __shfl_xor_sync(0xffffffffu, ss, o);
  }
  const float mu = s * (1.f / 256.f);
  const float var = ss * (1.f / 256.f) - mu * mu;
  const float rstd = rsqrtf(var + 1e-5f);

  float d0 = 0.f, d1 = 0.f;
#pragma unroll
  for (int j = 0; j < 4; ++j) {
    const int ch = lane * 2 + j * 64;
    const float2 g2 = *(const float2*)&ln2_g[ch];
    const float2 b2 = *(const float2*)&ln2_b[ch];
    const float2 w0 = *(const float2*)&pos_W[ch];
    const float2 w1 = *(const float2*)&pos_W[256 + ch];
    const float nh0 = (hn[j * 2] - mu) * rstd * g2.x + b2.x;
    const float nh1 = (hn[j * 2 + 1] - mu) * rstd * g2.y + b2.y;
    d0 += nh0 * w0.x + nh1 * w0.y;
    d1 += nh0 * w1.x + nh1 * w1.y;
  }
#pragma unroll
  for (int o = 16; o > 0; o >>= 1) {
    d0 += __shfl_xor_sync(0xffffffffu, d0, o);
    d1 += __shfl_xor_sync(0xffffffffu, d1, o);
  }
  const float r0 = sigm(d0 + pos_b[0]);
  const float r1 = sigm(d1 + pos_b[1]);
  if (lane == 0) {
    rel_out[(size_t)ped * 2 + 0] = r0;
    rel_out[(size_t)ped * 2 + 1] = r1;
  }

  // embed(rel) -> next x  (LN over 2 elems)
  const float d = 0.5f * (r0 - r1);
  const float inv = rsqrtf(d * d + 1e-5f);
  const float na =  d * inv * ln1_g[0] + ln1_b[0];
  const float nb = -d * inv * ln1_g[1] + ln1_b[1];
  __half* xp = g_x + (size_t)ped * E;
#pragma unroll
  for (int q = 0; q < 2; ++q) {
    const int j = lane * 2 + q;
    const float y = na * emb_W[j * 2 + 0] + nb * emb_W[j * 2 + 1] + emb_b[j];
    xp[j] = __float2half((y > 0.f) ? y : 0.01f * y);
  }
}

// ---------------------------------------------------------------------------
extern "C" void kernel_launch(void* const* d_in, const int* in_sizes, int n_in,
                              void* d_out, int out_size) {
  const float* last_pos_rel = (const float*)d_in[1];
  const float* h0   = (const float*)d_in[2];
  const float* c0   = (const float*)d_in[3];
  const float* W_ih = (const float*)d_in[4];
  const float* W_hh = (const float*)d_in[5];
  const float* b_ih = (const float*)d_in[6];
  const float* b_hh = (const float*)d_in[7];
  const float* emb_W = (const float*)d_in[8];
  const float* emb_b = (const float*)d_in[9];
  const float* ln1_g = (const float*)d_in[10];
  const float* ln1_b = (const float*)d_in[11];
  const float* pos_W = (const float*)d_in[12];
  const float* pos_b = (const float*)d_in[13];
  const float* ln2_g = (const float*)d_in[14];
  const float* ln2_b = (const float*)d_in[15];
  float* out = (float*)d_out;

  const int npeds = in_sizes[0] / 2;  // 8192

  static int smem_set = 0;
  if (!smem_set) {
    cudaFuncSetAttribute(gates_gemm, cudaFuncAttributeMaxDynamicSharedMemorySize,
                         SMEM_BYTES);
    smem_set = 1;
  }

  prep_weights<<<(G4 * KTOT + 255) / 256, 256>>>(W_ih, W_hh, b_ih, b_hh);
  init_state<<<(npeds * H + 255) / 256, 256>>>(h0, c0, npeds * H);
  embed_init<<<(npeds * E + 255) / 256, 256>>>(last_pos_rel, ln1_g, ln1_b, emb_W, emb_b, npeds);

  dim3 ggrid(G4 / 128, npeds / 128);
  for (int s = 0; s < SEQ; ++s) {
    gates_gemm<<<ggrid, 256, SMEM_BYTES>>>(npeds);
    lstm_fused<<<npeds / 8, 256>>>(ln2_g, ln2_b, pos_W, pos_b, emb_W, emb_b,
                                   ln1_g, ln1_b, out + (size_t)s * npeds * 2, npeds);
  }
}

// round 16
// speedup vs baseline: 1.5970x; 1.0288x over previous
#include <cuda_runtime.h>
#include <cuda_bf16.h>
#include <cuda_fp16.h>
#include <math.h>
#include <stdint.h>

#define NPEDS_MAX 8192
#define H 256
#define E 64
#define G4 1024   // 4*H
#define KTOT 320  // E + H
#define SEQ 30
#define KT_TILES 10  // KTOT/32

// ---- device-global scratch (no allocations allowed) ----
__device__ __align__(16) __half g_h[NPEDS_MAX * H];
__device__ __align__(16) float g_c[NPEDS_MAX * H];
__device__ __align__(16) __half g_x[NPEDS_MAX * E];
__device__ __align__(16) __half g_gates[NPEDS_MAX * G4];   // fp16 gates
__device__ __align__(16) __half g_Wn[G4 * KTOT];           // [n][k] fp16
__device__ __align__(16) float g_bias[G4];

__device__ __forceinline__ float sigm(float v) { return 1.f / (1.f + __expf(-v)); }
__device__ __forceinline__ float tanh_fast(float v) {
  return 2.f / (1.f + __expf(-2.f * v)) - 1.f;
}
// HW tanh (MUFU.TANH) — used ONLY on the output path (no c-recurrence).
__device__ __forceinline__ float tanh_ap(float x) {
  float y;
  asm("tanh.approx.f32 %0, %1;" : "=f"(y) : "f"(x));
  return y;
}
__device__ __forceinline__ float sigm_ap(float v) {
  return fmaf(tanh_ap(0.5f * v), 0.5f, 0.5f);
}

// ---------------------------------------------------------------------------
// Init kernels (run every graph replay -> deterministic state reset)
// ---------------------------------------------------------------------------
__global__ void prep_weights(const float* __restrict__ W_ih, const float* __restrict__ W_hh,
                             const float* __restrict__ b_ih, const float* __restrict__ b_hh) {
  int idx = blockIdx.x * blockDim.x + threadIdx.x;
  if (idx < G4 * KTOT) {
    int n = idx / KTOT, k = idx - n * KTOT;
    float w = (k < E) ? W_ih[n * E + k] : W_hh[n * H + (k - E)];
    g_Wn[idx] = __float2half(w);
  }
  if (idx < G4) g_bias[idx] = b_ih[idx] + b_hh[idx];
}

__global__ void init_state(const float* __restrict__ h0, const float* __restrict__ c0, int n) {
  int idx = blockIdx.x * blockDim.x + threadIdx.x;
  if (idx < n) { g_h[idx] = __float2half(h0[idx]); g_c[idx] = c0[idx]; }
}

// embed(p) = leaky_relu( LN_2(p) @ emb_W^T + emb_b )
__global__ void embed_init(const float* __restrict__ lpr,
                           const float* __restrict__ ln1_g, const float* __restrict__ ln1_b,
                           const float* __restrict__ emb_W, const float* __restrict__ emb_b,
                           int npeds) {
  int idx = blockIdx.x * blockDim.x + threadIdx.x;
  if (idx >= npeds * E) return;
  int ped = idx / E, j = idx - ped * E;
  float a = lpr[ped * 2 + 0], b = lpr[ped * 2 + 1];
  float d = 0.5f * (a - b);
  float inv = rsqrtf(d * d + 1e-5f);
  float na =  d * inv * ln1_g[0] + ln1_b[0];
  float nb = -d * inv * ln1_g[1] + ln1_b[1];
  float y = na * emb_W[j * 2 + 0] + nb * emb_W[j * 2 + 1] + emb_b[j];
  g_x[idx] = __float2half((y > 0.f) ? y : 0.01f * y);
}

// ---------------------------------------------------------------------------
// Per-step GEMM (fp16 MMA/accum, ldmatrix, 3-stage cp.async, small CTAs):
//   g_gates[M,1024](fp16) = [x|h][M,320] @ Wn^T
// BM=64, BN=128, BK=32. 128 threads = 4 warps (2m x 2n), warp tile 32x64.
// grid = 8 x 128 = 1024 CTAs; 5 CTAs/SM -> 20 warps/SM, fine-grain balance.
// ---------------------------------------------------------------------------
#define A_TILE_U 1280               // 64*20 uint32
#define B_TILE_U 2560               // 128*20 uint32
#define A_STAGE_B 5120              // bytes
#define B_STAGE_B 10240             // bytes
#define SMEM_BYTES (3 * (A_STAGE_B + B_STAGE_B))   // 46080

__global__ __launch_bounds__(128, 5) void gates_gemm(int npeds) {
  extern __shared__ __align__(16) uint32_t smem[];
  uint32_t* const As0 = smem;                   // [3][64][20]
  uint32_t* const Bs0 = smem + 3 * A_TILE_U;    // [3][128][20]

  const int bm = blockIdx.y * 64;
  const int bn = blockIdx.x * 128;
  const int t = threadIdx.x;
  const int warp = t >> 5;
  const int lane = t & 31;
  const int wm = (warp >> 1) * 32;   // 0 | 32
  const int wn = (warp & 1) * 64;    // 0 | 64
  const int gr = lane >> 2;   // 0..7  (store epilogue)
  const int lc = lane & 3;    // 0..3

  const int lg = lane >> 3;       // lane group 0..3
  const int lr = lane & 7;        // row within group
  const uint32_t aLane = (uint32_t)__cvta_generic_to_shared(
      &As0[(wm + (lg & 1) * 8 + lr) * 20 + (lg >> 1) * 4]);
  const uint32_t bLane = (uint32_t)__cvta_generic_to_shared(
      &Bs0[(wn + (lg >> 1) * 8 + lr) * 20 + (lg & 1) * 4]);

  uint32_t acc[2][8][2];          // f16x2 accumulators (32 regs)
#pragma unroll
  for (int i = 0; i < 2; ++i)
#pragma unroll
    for (int j = 0; j < 8; ++j) { acc[i][j][0] = 0u; acc[i][j][1] = 0u; }

  auto load_tile = [&](int kt, int stage) {
    const int k0 = kt * 32;
    const __half* srcA;
    int ldk, koff;
    if (k0 < E) { srcA = g_x; ldk = E; koff = k0; }
    else        { srcA = g_h; ldk = H; koff = k0 - E; }
    // A: 64 rows x 4 chunks = 256 chunks, 2 per thread
#pragma unroll
    for (int r = 0; r < 2; ++r) {
      const int idx = t + r * 128;
      const int row = idx >> 2, c = idx & 3;
      const void* gA = srcA + (size_t)(bm + row) * ldk + koff + c * 8;
      uint32_t dA = (uint32_t)__cvta_generic_to_shared(
          &As0[stage * A_TILE_U + row * 20 + c * 4]);
      asm volatile("cp.async.cg.shared.global [%0], [%1], 16;\n" :: "r"(dA), "l"(gA));
    }
    // B: 128 rows x 4 chunks = 512 chunks, 4 per thread
#pragma unroll
    for (int r = 0; r < 4; ++r) {
      const int idx = t + r * 128;
      const int row = idx >> 2, c = idx & 3;
      const void* gB = g_Wn + (size_t)(bn + row) * KTOT + k0 + c * 8;
      uint32_t dB = (uint32_t)__cvta_generic_to_shared(
          &Bs0[stage * B_TILE_U + row * 20 + c * 4]);
      asm volatile("cp.async.cg.shared.global [%0], [%1], 16;\n" :: "r"(dB), "l"(gB));
    }
    asm volatile("cp.async.commit_group;\n");
  };

  load_tile(0, 0);
  load_tile(1, 1);

#pragma unroll
  for (int kt = 0; kt < KT_TILES; ++kt) {
    if (kt + 1 < KT_TILES)
      asm volatile("cp.async.wait_group 1;\n" ::: "memory");
    else
      asm volatile("cp.async.wait_group 0;\n" ::: "memory");
    __syncthreads();
    if (kt + 2 < KT_TILES) load_tile(kt + 2, (kt + 2) % 3);

    const int stage = kt % 3;
    const uint32_t aSt = aLane + (uint32_t)stage * A_STAGE_B;
    const uint32_t bSt = bLane + (uint32_t)stage * B_STAGE_B;

#pragma unroll
    for (int ks = 0; ks < 2; ++ks) {
      const uint32_t kOff = (uint32_t)ks * 32u;
      uint32_t a[2][4], b[8][2];
#pragma unroll
      for (int mt = 0; mt < 2; ++mt) {
        asm volatile(
          "ldmatrix.sync.aligned.m8n8.x4.shared.b16 {%0,%1,%2,%3}, [%4];"
          : "=r"(a[mt][0]), "=r"(a[mt][1]), "=r"(a[mt][2]), "=r"(a[mt][3])
          : "r"(aSt + kOff + (uint32_t)mt * 1280u));   // 16 rows * 80B
      }
#pragma unroll
      for (int p = 0; p < 4; ++p) {
        asm volatile(
          "ldmatrix.sync.aligned.m8n8.x4.shared.b16 {%0,%1,%2,%3}, [%4];"
          : "=r"(b[2 * p][0]), "=r"(b[2 * p][1]),
            "=r"(b[2 * p + 1][0]), "=r"(b[2 * p + 1][1])
          : "r"(bSt + kOff + (uint32_t)p * 1280u));
      }
#pragma unroll
      for (int mt = 0; mt < 2; ++mt)
#pragma unroll
        for (int nt = 0; nt < 8; ++nt) {
          asm volatile(
            "mma.sync.aligned.m16n8k16.row.col.f16.f16.f16.f16 "
            "{%0,%1}, {%2,%3,%4,%5}, {%6,%7}, {%0,%1};"
            : "+r"(acc[mt][nt][0]), "+r"(acc[mt][nt][1])
            : "r"(a[mt][0]), "r"(a[mt][1]), "r"(a[mt][2]), "r"(a[mt][3]),
              "r"(b[nt][0]), "r"(b[nt][1]));
        }
    }
  }

  // ---- epilogue: accumulators ARE the fp16 gates; direct stores ----
#pragma unroll
  for (int mt = 0; mt < 2; ++mt) {
    const int row = bm + wm + mt * 16 + gr;
#pragma unroll
    for (int nt = 0; nt < 8; ++nt) {
      const int col = bn + wn + nt * 8 + lc * 2;
      *(uint32_t*)(g_gates + (size_t)row * G4 + col) = acc[mt][nt][0];
      *(uint32_t*)(g_gates + (size_t)(row + 8) * G4 + col) = acc[mt][nt][1];
    }
  }
}

// ---------------------------------------------------------------------------
// Fused per-step tail: LSTM elementwise + LN2 + pos projection (rel out) +
// embed(rel) -> next x. Channel-pair lanes -> all accesses 128B/warp.
// i/f/g gates: exact __expf path (c recurrence clean); o/tanh(cn): MUFU.TANH.
// ---------------------------------------------------------------------------
__global__ __launch_bounds__(256) void lstm_fused(
    const float* __restrict__ ln2_g, const float* __restrict__ ln2_b,
    const float* __restrict__ pos_W, const float* __restrict__ pos_b,
    const float* __restrict__ emb_W, const float* __restrict__ emb_b,
    const float* __restrict__ ln1_g, const float* __restrict__ ln1_b,
    float* __restrict__ rel_out, int npeds) {
  const int warp = threadIdx.x >> 5;
  const int lane = threadIdx.x & 31;
  const int ped = blockIdx.x * 8 + warp;
  if (ped >= npeds) return;

  const __half2* gp2 = (const __half2*)g_gates + (size_t)ped * (G4 / 2);
  float* cp = g_c + (size_t)ped * H;
  __half* hp = g_h + (size_t)ped * H;

  float hn[8];
  float s = 0.f, ss = 0.f;
#pragma unroll
  for (int j = 0; j < 4; ++j) {
    const int p2 = lane + j * 32;          // half2 index within a gate block
    const int ch = p2 * 2;                 // even channel
    const float2 gi = __half22float2(gp2[p2]);
    const float2 gf = __half22float2(gp2[128 + p2]);
    const float2 gg = __half22float2(gp2[256 + p2]);
    const float2 go = __half22float2(gp2[384 + p2]);
    const float2 bi = *(const float2*)&g_bias[ch];
    const float2 bf = *(const float2*)&g_bias[256 + ch];
    const float2 bg = *(const float2*)&g_bias[512 + ch];
    const float2 bo = *(const float2*)&g_bias[768 + ch];
    const float2 cv = *(const float2*)&cp[ch];

    const float cn0 = sigm(gf.x + bf.x) * cv.x + sigm(gi.x + bi.x) * tanh_fast(gg.x + bg.x);
    const float cn1 = sigm(gf.y + bf.y) * cv.y + sigm(gi.y + bi.y) * tanh_fast(gg.y + bg.y);
    const float hv0 = sigm_ap(go.x + bo.x) * tanh_ap(cn0);
    const float hv1 = sigm_ap(go.y + bo.y) * tanh_ap(cn1);
    *(float2*)&cp[ch] = make_float2(cn0, cn1);
    *(__half2*)&hp[ch] = __floats2half2_rn(hv0, hv1);
    hn[j * 2] = hv0; hn[j * 2 + 1] = hv1;
    s += hv0 + hv1;
    ss += hv0 * hv0 + hv1 * hv1;
  }
#pragma unroll
  for (int o = 16; o > 0; o >>= 1) {
    s += __shfl_xor_sync(0xffffffffu, s, o);
    ss += __shfl_xor_sync(0xffffffffu, ss, o);
  }
  const float mu = s * (1.f / 256.f);
  const float var = ss * (1.f / 256.f) - mu * mu;
  const float rstd = rsqrtf(var + 1e-5f);

  float d0 = 0.f, d1 = 0.f;
#pragma unroll
  for (int j = 0; j < 4; ++j) {
    const int ch = lane * 2 + j * 64;
    const float2 g2 = *(const float2*)&ln2_g[ch];
    const float2 b2 = *(const float2*)&ln2_b[ch];
    const float2 w0 = *(const float2*)&pos_W[ch];
    const float2 w1 = *(const float2*)&pos_W[256 + ch];
    const float nh0 = (hn[j * 2] - mu) * rstd * g2.x + b2.x;
    const float nh1 = (hn[j * 2 + 1] - mu) * rstd * g2.y + b2.y;
    d0 += nh0 * w0.x + nh1 * w0.y;
    d1 += nh0 * w1.x + nh1 * w1.y;
  }
#pragma unroll
  for (int o = 16; o > 0; o >>= 1) {
    d0 += __shfl_xor_sync(0xffffffffu, d0, o);
    d1 += __shfl_xor_sync(0xffffffffu, d1, o);
  }
  const float r0 = sigm(d0 + pos_b[0]);
  const float r1 = sigm(d1 + pos_b[1]);
  if (lane == 0) {
    rel_out[(size_t)ped * 2 + 0] = r0;
    rel_out[(size_t)ped * 2 + 1] = r1;
  }

  // embed(rel) -> next x  (LN over 2 elems)
  const float d = 0.5f * (r0 - r1);
  const float inv = rsqrtf(d * d + 1e-5f);
  const float na =  d * inv * ln1_g[0] + ln1_b[0];
  const float nb = -d * inv * ln1_g[1] + ln1_b[1];
  __half* xp = g_x + (size_t)ped * E;
#pragma unroll
  for (int q = 0; q < 2; ++q) {
    const int j = lane * 2 + q;
    const float y = na * emb_W[j * 2 + 0] + nb * emb_W[j * 2 + 1] + emb_b[j];
    xp[j] = __float2half((y > 0.f) ? y : 0.01f * y);
  }
}

// ---------------------------------------------------------------------------
extern "C" void kernel_launch(void* const* d_in, const int* in_sizes, int n_in,
                              void* d_out, int out_size) {
  const float* last_pos_rel = (const float*)d_in[1];
  const float* h0   = (const float*)d_in[2];
  const float* c0   = (const float*)d_in[3];
  const float* W_ih = (const float*)d_in[4];
  const float* W_hh = (const float*)d_in[5];
  const float* b_ih = (const float*)d_in[6];
  const float* b_hh = (const float*)d_in[7];
  const float* emb_W = (const float*)d_in[8];
  const float* emb_b = (const float*)d_in[9];
  const float* ln1_g = (const float*)d_in[10];
  const float* ln1_b = (const float*)d_in[11];
  const float* pos_W = (const float*)d_in[12];
  const float* pos_b = (const float*)d_in[13];
  const float* ln2_g = (const float*)d_in[14];
  const float* ln2_b = (const float*)d_in[15];
  float* out = (float*)d_out;

  const int npeds = in_sizes[0] / 2;  // 8192

  static int smem_set = 0;
  if (!smem_set) {
    cudaFuncSetAttribute(gates_gemm, cudaFuncAttributeMaxDynamicSharedMemorySize,
                         SMEM_BYTES);
    smem_set = 1;
  }

  prep_weights<<<(G4 * KTOT + 255) / 256, 256>>>(W_ih, W_hh, b_ih, b_hh);
  init_state<<<(npeds * H + 255) / 256, 256>>>(h0, c0, npeds * H);
  embed_init<<<(npeds * E + 255) / 256, 256>>>(last_pos_rel, ln1_g, ln1_b, emb_W, emb_b, npeds);

  dim3 ggrid(G4 / 128, npeds / 64);   // 8 x 128 = 1024 CTAs
  for (int s = 0; s < SEQ; ++s) {
    gates_gemm<<<ggrid, 128, SMEM_BYTES>>>(npeds);
    lstm_fused<<<npeds / 8, 256>>>(ln2_g, ln2_b, pos_W, pos_b, emb_W, emb_b,
                                   ln1_g, ln1_b, out + (size_t)s * npeds * 2, npeds);
  }
}